// round 4
// baseline (speedup 1.0000x reference)
#include <cuda_runtime.h>
#include <cuda_bf16.h>
#include <cstdint>

// Problem constants
#define SEQ   2048
#define HDIM  4096
#define NH    32
#define NKV   8
#define HD    128

// ---------------------------------------------------------------------------
// Scratch (no cudaMalloc allowed -> __device__ globals)
// ---------------------------------------------------------------------------
__device__ float g_Hq[SEQ * HDIM];   // hidden gathered by q_order_col
__device__ float g_Hk[SEQ * HDIM];
__device__ float g_Hv[SEQ * HDIM];
__device__ float g_Q [SEQ * NH  * HD];
__device__ float g_K [SEQ * NKV * HD];
__device__ float g_V [SEQ * NKV * HD];
__device__ float g_A [SEQ * NH  * HD];  // attention output [t, h*128+d]
__device__ float g_Ap[SEQ * NH  * HD];  // gathered by o_order_col

// ---------------------------------------------------------------------------
// Column gather: out[t, c] = in[t, idx[c]]   (H = 4096 fixed)
// ---------------------------------------------------------------------------
__global__ void __launch_bounds__(256) gather_cols_kernel(
    const float* __restrict__ in, const int* __restrict__ idx,
    float* __restrict__ out) {
  int t = blockIdx.y;
  int c = blockIdx.x * 256 + threadIdx.x;
  out[(size_t)t * HDIM + c] = in[(size_t)t * HDIM + idx[c]];
}

// ---------------------------------------------------------------------------
// Row-gathered GEMM: C[t, j] = sum_c A[t, c] * W[row_idx[j], c]
// A: [2048, Kd] row-major (pre-gathered), W: [*, Kd] row-major, C: [2048, N]
// BM=64 BN=64 BK=16, 256 threads, 4x4 register tile per thread.
// ---------------------------------------------------------------------------
__global__ void __launch_bounds__(256) gemm_rg_kernel(
    const float* __restrict__ A, const float* __restrict__ W,
    const int* __restrict__ row_idx, float* __restrict__ C,
    int N, int Kd) {
  __shared__ float As[16][64];
  __shared__ float Bs[16][64];
  __shared__ int   rows[64];
  const int bm = blockIdx.y, bn = blockIdx.x;
  const int tid = threadIdx.x;
  const int tx = tid & 15, ty = tid >> 4;
  if (tid < 64) rows[tid] = row_idx[bn * 64 + tid];
  __syncthreads();

  const int lm = tid >> 2;            // 0..63
  const int kq = (tid & 3) * 4;       // 0,4,8,12
  const float* Arow = A + (size_t)(bm * 64 + lm) * Kd;
  const float* Wrow = W + (size_t)rows[lm] * Kd;

  float acc[4][4] = {};
  for (int c0 = 0; c0 < Kd; c0 += 16) {
    float4 av = *(const float4*)(Arow + c0 + kq);
    float4 bv = *(const float4*)(Wrow + c0 + kq);
    __syncthreads();
    As[kq + 0][lm] = av.x; As[kq + 1][lm] = av.y;
    As[kq + 2][lm] = av.z; As[kq + 3][lm] = av.w;
    Bs[kq + 0][lm] = bv.x; Bs[kq + 1][lm] = bv.y;
    Bs[kq + 2][lm] = bv.z; Bs[kq + 3][lm] = bv.w;
    __syncthreads();
#pragma unroll
    for (int k = 0; k < 16; k++) {
      float4 a = *(const float4*)&As[k][ty * 4];
      float4 b = *(const float4*)&Bs[k][tx * 4];
      acc[0][0] += a.x * b.x; acc[0][1] += a.x * b.y; acc[0][2] += a.x * b.z; acc[0][3] += a.x * b.w;
      acc[1][0] += a.y * b.x; acc[1][1] += a.y * b.y; acc[1][2] += a.y * b.z; acc[1][3] += a.y * b.w;
      acc[2][0] += a.z * b.x; acc[2][1] += a.z * b.y; acc[2][2] += a.z * b.z; acc[2][3] += a.z * b.w;
      acc[3][0] += a.w * b.x; acc[3][1] += a.w * b.y; acc[3][2] += a.w * b.z; acc[3][3] += a.w * b.w;
    }
  }
#pragma unroll
  for (int i = 0; i < 4; i++) {
    float* Crow = C + (size_t)(bm * 64 + ty * 4 + i) * N + bn * 64 + tx * 4;
    *(float4*)Crow = make_float4(acc[i][0], acc[i][1], acc[i][2], acc[i][3]);
  }
}

// ---------------------------------------------------------------------------
// RoPE (in-place). x: [2048, nheads*128], cos/sin: [2048, 128]
// out[d]    = x[d]*cos[d]    - x[d+64]*sin[d]
// out[d+64] = x[d+64]*cos[d+64] + x[d]*sin[d+64]
// ---------------------------------------------------------------------------
__global__ void __launch_bounds__(256) rope_kernel(
    float* __restrict__ x, const float* __restrict__ cs,
    const float* __restrict__ sn, int nheads) {
  int idx = blockIdx.x * 256 + threadIdx.x;  // over 2048*nheads*64
  int d = idx & 63;
  int h = (idx >> 6) % nheads;
  int t = idx / (64 * nheads);
  float c1 = cs[t * 128 + d],      s1 = sn[t * 128 + d];
  float c2 = cs[t * 128 + d + 64], s2 = sn[t * 128 + d + 64];
  float* row = x + (size_t)t * (nheads * 128) + h * 128;
  float x1 = row[d], x2 = row[d + 64];
  row[d]      = x1 * c1 - x2 * s1;
  row[d + 64] = x2 * c2 + x1 * s2;
}

// ---------------------------------------------------------------------------
// Causal flash attention, fp32. BM=32 q-rows per block, BN=64 keys per tile.
// grid = (64 q-tiles, 32 heads), 256 threads (16x16).
// Thread (tx,ty): S rows {2ty, 2ty+1} x cols {4tx..4tx+3};
//                 O rows {2ty, 2ty+1} x cols {8tx..8tx+7}.
// ---------------------------------------------------------------------------
__global__ void __launch_bounds__(256) flash_kernel(
    const float* __restrict__ Q, const float* __restrict__ K,
    const float* __restrict__ V, float* __restrict__ O) {
  __shared__ float Qs[32][129];   // pad 129 -> conflict-free row-broadcast reads
  __shared__ float Ps[32][65];
  __shared__ float Ks[16][64];
  __shared__ float Vs[16][128];

  const int h = blockIdx.y;
  const int kvh = h >> 2;                 // GQA: rep = 32/8 = 4
  const int qbase = blockIdx.x * 32;
  const int tid = threadIdx.x;
  const int tx = tid & 15, ty = tid >> 4;

  const float* Qg = Q + (size_t)qbase * (NH * HD) + h * HD;
#pragma unroll
  for (int i = 0; i < 4; i++) {
    int idx = i * 256 + tid;
    int m = idx >> 5, d4 = (idx & 31) * 4;
    float4 v = *(const float4*)(Qg + (size_t)m * (NH * HD) + d4);
    Qs[m][d4] = v.x; Qs[m][d4 + 1] = v.y; Qs[m][d4 + 2] = v.z; Qs[m][d4 + 3] = v.w;
  }
  __syncthreads();

  float m_i[2] = {-1e30f, -1e30f};
  float l_i[2] = {0.f, 0.f};
  float o[2][8] = {};

  const int ktmax = (qbase + 31) >> 6;
  const float* Kg = K + kvh * HD;
  const float* Vg = V + kvh * HD;
  const float scale = 0.08838834764831845f;  // 1/sqrt(128)

  const int kn = tid >> 2;         // 0..63
  const int kq = (tid & 3) * 4;    // 0,4,8,12

  for (int kt = 0; kt <= ktmax; kt++) {
    const int kbase = kt * 64;
    float s[2][4] = {};
    for (int dc = 0; dc < 128; dc += 16) {
      float4 kv = *(const float4*)(Kg + (size_t)(kbase + kn) * (NKV * HD) + dc + kq);
      __syncthreads();
      Ks[kq + 0][kn] = kv.x; Ks[kq + 1][kn] = kv.y;
      Ks[kq + 2][kn] = kv.z; Ks[kq + 3][kn] = kv.w;
      __syncthreads();
#pragma unroll
      for (int k = 0; k < 16; k++) {
        float a0 = Qs[ty * 2][dc + k];
        float a1 = Qs[ty * 2 + 1][dc + k];
        float4 b = *(const float4*)&Ks[k][tx * 4];
        s[0][0] += a0 * b.x; s[0][1] += a0 * b.y; s[0][2] += a0 * b.z; s[0][3] += a0 * b.w;
        s[1][0] += a1 * b.x; s[1][1] += a1 * b.y; s[1][2] += a1 * b.z; s[1][3] += a1 * b.w;
      }
    }
    const bool diag = (kt == ktmax);
#pragma unroll
    for (int i = 0; i < 2; i++) {
      int qg = qbase + ty * 2 + i;
      float rm = -1e30f;
#pragma unroll
      for (int j = 0; j < 4; j++) {
        float v = s[i][j] * scale;
        if (diag && (kbase + tx * 4 + j) > qg) v = -1e30f;
        s[i][j] = v;
        rm = fmaxf(rm, v);
      }
#pragma unroll
      for (int off = 8; off; off >>= 1)
        rm = fmaxf(rm, __shfl_xor_sync(0xffffffffu, rm, off));
      float mnew = fmaxf(m_i[i], rm);
      float corr = __expf(m_i[i] - mnew);
      float rs = 0.f;
#pragma unroll
      for (int j = 0; j < 4; j++) {
        float p = __expf(s[i][j] - mnew);
        Ps[ty * 2 + i][tx * 4 + j] = p;
        rs += p;
      }
#pragma unroll
      for (int off = 8; off; off >>= 1)
        rs += __shfl_xor_sync(0xffffffffu, rs, off);
      l_i[i] = l_i[i] * corr + rs;
      m_i[i] = mnew;
#pragma unroll
      for (int j = 0; j < 8; j++) o[i][j] *= corr;
    }
    // O += P * V  (V tile streamed in 16-row chunks)
    for (int kc = 0; kc < 64; kc += 16) {
      float4 vv[2];
#pragma unroll
      for (int r = 0; r < 2; r++) {
        int idx = r * 256 + tid;
        int kk = idx >> 5, d4 = (idx & 31) * 4;
        vv[r] = *(const float4*)(Vg + (size_t)(kbase + kc + kk) * (NKV * HD) + d4);
      }
      __syncthreads();   // old Vs reads done; also orders Ps writes before reads
#pragma unroll
      for (int r = 0; r < 2; r++) {
        int idx = r * 256 + tid;
        int kk = idx >> 5, d4 = (idx & 31) * 4;
        Vs[kk][d4] = vv[r].x; Vs[kk][d4 + 1] = vv[r].y;
        Vs[kk][d4 + 2] = vv[r].z; Vs[kk][d4 + 3] = vv[r].w;
      }
      __syncthreads();
#pragma unroll
      for (int kk = 0; kk < 16; kk++) {
        float p0 = Ps[ty * 2][kc + kk];
        float p1 = Ps[ty * 2 + 1][kc + kk];
        float4 v0 = *(const float4*)&Vs[kk][tx * 8];
        float4 v1 = *(const float4*)&Vs[kk][tx * 8 + 4];
        o[0][0] += p0 * v0.x; o[0][1] += p0 * v0.y; o[0][2] += p0 * v0.z; o[0][3] += p0 * v0.w;
        o[0][4] += p0 * v1.x; o[0][5] += p0 * v1.y; o[0][6] += p0 * v1.z; o[0][7] += p0 * v1.w;
        o[1][0] += p1 * v0.x; o[1][1] += p1 * v0.y; o[1][2] += p1 * v0.z; o[1][3] += p1 * v0.w;
        o[1][4] += p1 * v1.x; o[1][5] += p1 * v1.y; o[1][6] += p1 * v1.z; o[1][7] += p1 * v1.w;
      }
      __syncthreads();
    }
  }
#pragma unroll
  for (int i = 0; i < 2; i++) {
    float rl = 1.0f / l_i[i];
    float* Orow = O + (size_t)(qbase + ty * 2 + i) * (NH * HD) + h * HD + tx * 8;
    *(float4*)(Orow)     = make_float4(o[i][0] * rl, o[i][1] * rl, o[i][2] * rl, o[i][3] * rl);
    *(float4*)(Orow + 4) = make_float4(o[i][4] * rl, o[i][5] * rl, o[i][6] * rl, o[i][7] * rl);
  }
}

// ---------------------------------------------------------------------------
// Host launcher
// ---------------------------------------------------------------------------
extern "C" void kernel_launch(void* const* d_in, const int* in_sizes, int n_in,
                              void* d_out, int out_size) {
  const float* hidden = (const float*)d_in[0];
  const float* Wq = (const float*)d_in[1];
  const float* Wk = (const float*)d_in[2];
  const float* Wv = (const float*)d_in[3];
  const float* Wo = (const float*)d_in[4];
  const float* cosp = (const float*)d_in[5];
  const float* sinp = (const float*)d_in[6];
  // d_in[7] attention_mask: exactly causal with -1e9 -> handled analytically
  const int* qcol = (const int*)d_in[8];
  const int* qrow = (const int*)d_in[9];
  const int* kcol = (const int*)d_in[10];
  const int* krow = (const int*)d_in[11];
  const int* vcol = (const int*)d_in[12];
  const int* vrow = (const int*)d_in[13];
  const int* ocol = (const int*)d_in[14];
  const int* orow = (const int*)d_in[15];

  float *Hq, *Hk, *Hv, *Qb, *Kb, *Vb, *Ab, *Ap;
  cudaGetSymbolAddress((void**)&Hq, g_Hq);
  cudaGetSymbolAddress((void**)&Hk, g_Hk);
  cudaGetSymbolAddress((void**)&Hv, g_Hv);
  cudaGetSymbolAddress((void**)&Qb, g_Q);
  cudaGetSymbolAddress((void**)&Kb, g_K);
  cudaGetSymbolAddress((void**)&Vb, g_V);
  cudaGetSymbolAddress((void**)&Ab, g_A);
  cudaGetSymbolAddress((void**)&Ap, g_Ap);

  dim3 gth(HDIM / 256, SEQ);
  gather_cols_kernel<<<gth, 256>>>(hidden, qcol, Hq);
  gather_cols_kernel<<<gth, 256>>>(hidden, kcol, Hk);
  gather_cols_kernel<<<gth, 256>>>(hidden, vcol, Hv);

  gemm_rg_kernel<<<dim3(64, 32), 256>>>(Hq, Wq, qrow, Qb, NH * HD, HDIM);
  gemm_rg_kernel<<<dim3(16, 32), 256>>>(Hk, Wk, krow, Kb, NKV * HD, HDIM);
  gemm_rg_kernel<<<dim3(16, 32), 256>>>(Hv, Wv, vrow, Vb, NKV * HD, HDIM);

  rope_kernel<<<(SEQ * NH * 64) / 256, 256>>>(Qb, cosp, sinp, NH);
  rope_kernel<<<(SEQ * NKV * 64) / 256, 256>>>(Kb, cosp, sinp, NKV);

  flash_kernel<<<dim3(SEQ / 32, NH), 256>>>(Qb, Kb, Vb, Ab);

  gather_cols_kernel<<<gth, 256>>>(Ab, ocol, Ap);
  gemm_rg_kernel<<<dim3(64, 32), 256>>>(Ap, Wo, orow, (float*)d_out, NH * HD, HDIM);
}

// round 6
// speedup vs baseline: 1.1357x; 1.1357x over previous
#include <cuda_runtime.h>
#include <cuda_bf16.h>
#include <cstdint>

#define SEQ   2048
#define HDIM  4096
#define NH    32
#define NKV   8
#define HD    128

// ---------------------------------------------------------------------------
// Scratch (__device__ globals; no cudaMalloc allowed)
// ---------------------------------------------------------------------------
__device__ __nv_bfloat16 g_hq_h[SEQ * HDIM], g_hq_l[SEQ * HDIM];
__device__ __nv_bfloat16 g_hk_h[SEQ * HDIM], g_hk_l[SEQ * HDIM];
__device__ __nv_bfloat16 g_hv_h[SEQ * HDIM], g_hv_l[SEQ * HDIM];
__device__ __nv_bfloat16 g_ao_h[SEQ * HDIM], g_ao_l[SEQ * HDIM];
__device__ __nv_bfloat16 g_wq_h[4096 * 4096], g_wq_l[4096 * 4096];
__device__ __nv_bfloat16 g_wk_h[1024 * 4096], g_wk_l[1024 * 4096];
__device__ __nv_bfloat16 g_wv_h[1024 * 4096], g_wv_l[1024 * 4096];
__device__ __nv_bfloat16 g_wo_h[4096 * 4096], g_wo_l[4096 * 4096];
__device__ float g_Q[SEQ * NH * HD];
__device__ float g_K[SEQ * NKV * HD];
__device__ float g_V[SEQ * NKV * HD];
__device__ float g_A[SEQ * NH * HD];

// ---------------------------------------------------------------------------
// PTX helpers (baseline PTX only -- no sm_103a-specific instructions!)
// ---------------------------------------------------------------------------
static __device__ __forceinline__ uint32_t smem_u32(const void* p) {
  uint32_t a;
  asm("{ .reg .u64 t; cvta.to.shared.u64 t, %1; cvt.u32.u64 %0, t; }"
      : "=r"(a) : "l"(p));
  return a;
}

#define CP_ASYNC16(dst, src) \
  asm volatile("cp.async.cg.shared.global [%0], [%1], 16;" :: "r"(dst), "l"(src))
#define CP_COMMIT()   asm volatile("cp.async.commit_group;" ::: "memory")
#define CP_WAIT(n)    asm volatile("cp.async.wait_group %0;" :: "n"(n) : "memory")

static __device__ __forceinline__ void ldsm_x4(uint32_t* r, uint32_t addr) {
  asm volatile("ldmatrix.sync.aligned.m8n8.x4.shared.b16 {%0,%1,%2,%3}, [%4];"
               : "=r"(r[0]), "=r"(r[1]), "=r"(r[2]), "=r"(r[3]) : "r"(addr));
}

static __device__ __forceinline__ void mma_bf16(float* d, const uint32_t* a,
                                                const uint32_t* b) {
  asm volatile(
      "mma.sync.aligned.m16n8k16.row.col.f32.bf16.bf16.f32 "
      "{%0,%1,%2,%3}, {%4,%5,%6,%7}, {%8,%9}, {%0,%1,%2,%3};"
      : "+f"(d[0]), "+f"(d[1]), "+f"(d[2]), "+f"(d[3])
      : "r"(a[0]), "r"(a[1]), "r"(a[2]), "r"(a[3]), "r"(b[0]), "r"(b[1]));
}

// ---------------------------------------------------------------------------
// Conversion kernels (fold column/row permutations into fp32 -> bf16 hi/lo)
// ---------------------------------------------------------------------------
__global__ void __launch_bounds__(256) gather_convert_kernel(
    const float* __restrict__ in, const int* __restrict__ idx,
    __nv_bfloat16* __restrict__ oh, __nv_bfloat16* __restrict__ ol) {
  int t = blockIdx.y;
  int c = blockIdx.x * 256 + threadIdx.x;
  float v = in[(size_t)t * HDIM + idx[c]];
  __nv_bfloat16 h = __float2bfloat16(v);
  oh[(size_t)t * HDIM + c] = h;
  ol[(size_t)t * HDIM + c] = __float2bfloat16(v - __bfloat162float(h));
}

__global__ void __launch_bounds__(256) wconvert_kernel(
    const float* __restrict__ W, const int* __restrict__ ridx,
    __nv_bfloat16* __restrict__ oh, __nv_bfloat16* __restrict__ ol) {
  int j = blockIdx.y;
  int c = blockIdx.x * 256 + threadIdx.x;
  float v = W[(size_t)ridx[j] * HDIM + c];
  __nv_bfloat16 h = __float2bfloat16(v);
  oh[(size_t)j * HDIM + c] = h;
  ol[(size_t)j * HDIM + c] = __float2bfloat16(v - __bfloat162float(h));
}

// ---------------------------------------------------------------------------
// Split-bf16 tensor-core GEMM via mma.sync (legal on plain sm_103):
//   C[2048, Ntot] = (Ah+Al)[2048,4096] @ (Bh+Bl)[Ntot,4096]^T
//   acc += Ah*Bh + Ah*Bl + Al*Bh   (fp32 accumulate; Al*Bl ~2^-18, dropped)
// Tiles: BM=128, BN=128, BK=32. 8 warps, each computes 32(M) x 64(N).
// Smem rows padded to 40 bf16 (80B) -> conflict-free ldmatrix.
// Stage = 4 matrices * 128 rows * 80B = 40960B; double buffered.
// ---------------------------------------------------------------------------
#define STAGE_B 40960
#define GEMM_SMEM (2 * STAGE_B)

__global__ void __launch_bounds__(256, 1) gemm_mma_kernel(
    const __nv_bfloat16* __restrict__ Ah, const __nv_bfloat16* __restrict__ Al,
    const __nv_bfloat16* __restrict__ Bh, const __nv_bfloat16* __restrict__ Bl,
    float* __restrict__ C, int Ntot) {
  extern __shared__ __align__(1024) char smem[];
  uint32_t sb = smem_u32(smem);
  const int tid = threadIdx.x, wid = tid >> 5, lane = tid & 31;
  const int row0 = blockIdx.x * 128, col0 = blockIdx.y * 128;

  // Per-thread cp.async descriptors: 2048 16B-chunks/stage, 8 per thread.
  // chunk t: mat = t>>9 (Ah,Al,Bh,Bl), r = (t>>2)&127, c = t&3
  const __nv_bfloat16* ld_src[8];
  uint32_t ld_dst[8];
#pragma unroll
  for (int i = 0; i < 8; i++) {
    int t = i * 256 + tid;
    int mat = t >> 9, r = (t >> 2) & 127, c = t & 3;
    const __nv_bfloat16* base =
        (mat == 0) ? Ah + (size_t)row0 * 4096 :
        (mat == 1) ? Al + (size_t)row0 * 4096 :
        (mat == 2) ? Bh + (size_t)col0 * 4096 :
                     Bl + (size_t)col0 * 4096;
    ld_src[i] = base + (size_t)r * 4096 + c * 8;
    ld_dst[i] = (uint32_t)(mat * 10240 + r * 80 + c * 16);
  }

  // Warp tile: m0 in {0,32,64,96}, n0 in {0,64}
  const int m0 = (wid & 3) * 32, n0 = (wid >> 2) * 64;
  // ldmatrix per-lane row/k offsets
  // A x4: matrices (m0..7,k0)(m8..15,k0)(m0..7,k8)(m8..15,k8)
  const uint32_t a_lrow = (lane & 7) + ((lane >> 3) & 1) * 8;
  const uint32_t a_lk   = ((lane >> 4) & 1) * 8;
  // B x4: matrices (n0..7,k0)(n0..7,k8)(n8..15,k0)(n8..15,k8)
  const uint32_t b_lrow = (lane & 7) + ((lane >> 4) & 1) * 8;
  const uint32_t b_lk   = ((lane >> 3) & 1) * 8;

  float acc[2][8][4];
#pragma unroll
  for (int mt = 0; mt < 2; mt++)
#pragma unroll
    for (int nt = 0; nt < 8; nt++)
#pragma unroll
      for (int j = 0; j < 4; j++) acc[mt][nt][j] = 0.f;

  // preload stage 0
#pragma unroll
  for (int i = 0; i < 8; i++) CP_ASYNC16(sb + ld_dst[i], ld_src[i]);
  CP_COMMIT();

#pragma unroll 1
  for (int kc = 0; kc < 128; kc++) {
    const int p = kc & 1;
    if (kc + 1 < 128) {
      const uint32_t qb = sb + (p ^ 1) * STAGE_B;
      const int ko = (kc + 1) * 32;
#pragma unroll
      for (int i = 0; i < 8; i++) CP_ASYNC16(qb + ld_dst[i], ld_src[i] + ko);
      CP_COMMIT();
      CP_WAIT(1);
    } else {
      CP_WAIT(0);
    }
    __syncthreads();

    const uint32_t base = sb + p * STAGE_B;
#pragma unroll
    for (int ks = 0; ks < 32; ks += 16) {
      uint32_t ah[2][4], al[2][4];
#pragma unroll
      for (int mt = 0; mt < 2; mt++) {
        uint32_t ro = (m0 + mt * 16 + a_lrow) * 80 + (ks + a_lk) * 2;
        ldsm_x4(ah[mt], base + ro);
        ldsm_x4(al[mt], base + 10240 + ro);
      }
      uint32_t bh[8][2], bl[8][2];
#pragma unroll
      for (int nt2 = 0; nt2 < 4; nt2++) {
        uint32_t ro = (n0 + nt2 * 16 + b_lrow) * 80 + (ks + b_lk) * 2;
        uint32_t t0[4], t1[4];
        ldsm_x4(t0, base + 20480 + ro);
        ldsm_x4(t1, base + 30720 + ro);
        bh[nt2 * 2][0] = t0[0]; bh[nt2 * 2][1] = t0[1];
        bh[nt2 * 2 + 1][0] = t0[2]; bh[nt2 * 2 + 1][1] = t0[3];
        bl[nt2 * 2][0] = t1[0]; bl[nt2 * 2][1] = t1[1];
        bl[nt2 * 2 + 1][0] = t1[2]; bl[nt2 * 2 + 1][1] = t1[3];
      }
#pragma unroll
      for (int mt = 0; mt < 2; mt++)
#pragma unroll
        for (int nt = 0; nt < 8; nt++) {
          mma_bf16(acc[mt][nt], ah[mt], bh[nt]);
          mma_bf16(acc[mt][nt], ah[mt], bl[nt]);
          mma_bf16(acc[mt][nt], al[mt], bh[nt]);
        }
    }
    __syncthreads();
  }

  // Epilogue: c0,c1 -> (m, n..n+1); c2,c3 -> (m+8, n..n+1)
#pragma unroll
  for (int mt = 0; mt < 2; mt++)
#pragma unroll
    for (int nt = 0; nt < 8; nt++) {
      int m = row0 + m0 + mt * 16 + (lane >> 2);
      int n = col0 + n0 + nt * 8 + (lane & 3) * 2;
      *(float2*)&C[(size_t)m * Ntot + n] =
          make_float2(acc[mt][nt][0], acc[mt][nt][1]);
      *(float2*)&C[(size_t)(m + 8) * Ntot + n] =
          make_float2(acc[mt][nt][2], acc[mt][nt][3]);
    }
}

// ---------------------------------------------------------------------------
// RoPE (in-place, fp32)
// ---------------------------------------------------------------------------
__global__ void __launch_bounds__(256) rope_kernel(
    float* __restrict__ x, const float* __restrict__ cs,
    const float* __restrict__ sn, int nheads) {
  int idx = blockIdx.x * 256 + threadIdx.x;
  int d = idx & 63;
  int h = (idx >> 6) % nheads;
  int t = idx / (64 * nheads);
  float c1 = cs[t * 128 + d],      s1 = sn[t * 128 + d];
  float c2 = cs[t * 128 + d + 64], s2 = sn[t * 128 + d + 64];
  float* row = x + (size_t)t * (nheads * 128) + h * 128;
  float x1 = row[d], x2 = row[d + 64];
  row[d]      = x1 * c1 - x2 * s1;
  row[d + 64] = x2 * c2 + x1 * s2;
}

// ---------------------------------------------------------------------------
// Causal flash attention, fp32 (unchanged from passing round)
// ---------------------------------------------------------------------------
__global__ void __launch_bounds__(256) flash_kernel(
    const float* __restrict__ Q, const float* __restrict__ K,
    const float* __restrict__ V, float* __restrict__ O) {
  __shared__ float Qs[32][129];
  __shared__ float Ps[32][65];
  __shared__ float Ks[16][64];
  __shared__ float Vs[16][128];

  const int h = blockIdx.y;
  const int kvh = h >> 2;
  const int qbase = blockIdx.x * 32;
  const int tid = threadIdx.x;
  const int tx = tid & 15, ty = tid >> 4;

  const float* Qg = Q + (size_t)qbase * (NH * HD) + h * HD;
#pragma unroll
  for (int i = 0; i < 4; i++) {
    int idx = i * 256 + tid;
    int m = idx >> 5, d4 = (idx & 31) * 4;
    float4 v = *(const float4*)(Qg + (size_t)m * (NH * HD) + d4);
    Qs[m][d4] = v.x; Qs[m][d4 + 1] = v.y; Qs[m][d4 + 2] = v.z; Qs[m][d4 + 3] = v.w;
  }
  __syncthreads();

  float m_i[2] = {-1e30f, -1e30f};
  float l_i[2] = {0.f, 0.f};
  float o[2][8] = {};

  const int ktmax = (qbase + 31) >> 6;
  const float* Kg = K + kvh * HD;
  const float* Vg = V + kvh * HD;
  const float scale = 0.08838834764831845f;

  const int kn = tid >> 2;
  const int kq = (tid & 3) * 4;

  for (int kt = 0; kt <= ktmax; kt++) {
    const int kbase = kt * 64;
    float s[2][4] = {};
    for (int dc = 0; dc < 128; dc += 16) {
      float4 kv = *(const float4*)(Kg + (size_t)(kbase + kn) * (NKV * HD) + dc + kq);
      __syncthreads();
      Ks[kq + 0][kn] = kv.x; Ks[kq + 1][kn] = kv.y;
      Ks[kq + 2][kn] = kv.z; Ks[kq + 3][kn] = kv.w;
      __syncthreads();
#pragma unroll
      for (int k = 0; k < 16; k++) {
        float a0 = Qs[ty * 2][dc + k];
        float a1 = Qs[ty * 2 + 1][dc + k];
        float4 b = *(const float4*)&Ks[k][tx * 4];
        s[0][0] += a0 * b.x; s[0][1] += a0 * b.y; s[0][2] += a0 * b.z; s[0][3] += a0 * b.w;
        s[1][0] += a1 * b.x; s[1][1] += a1 * b.y; s[1][2] += a1 * b.z; s[1][3] += a1 * b.w;
      }
    }
    const bool diag = (kt == ktmax);
#pragma unroll
    for (int i = 0; i < 2; i++) {
      int qg = qbase + ty * 2 + i;
      float rm = -1e30f;
#pragma unroll
      for (int j = 0; j < 4; j++) {
        float v = s[i][j] * scale;
        if (diag && (kbase + tx * 4 + j) > qg) v = -1e30f;
        s[i][j] = v;
        rm = fmaxf(rm, v);
      }
#pragma unroll
      for (int off = 8; off; off >>= 1)
        rm = fmaxf(rm, __shfl_xor_sync(0xffffffffu, rm, off));
      float mnew = fmaxf(m_i[i], rm);
      float corr = __expf(m_i[i] - mnew);
      float rs = 0.f;
#pragma unroll
      for (int j = 0; j < 4; j++) {
        float p = __expf(s[i][j] - mnew);
        Ps[ty * 2 + i][tx * 4 + j] = p;
        rs += p;
      }
#pragma unroll
      for (int off = 8; off; off >>= 1)
        rs += __shfl_xor_sync(0xffffffffu, rs, off);
      l_i[i] = l_i[i] * corr + rs;
      m_i[i] = mnew;
#pragma unroll
      for (int j = 0; j < 8; j++) o[i][j] *= corr;
    }
    for (int kc = 0; kc < 64; kc += 16) {
      float4 vv[2];
#pragma unroll
      for (int r = 0; r < 2; r++) {
        int idx = r * 256 + tid;
        int kk = idx >> 5, d4 = (idx & 31) * 4;
        vv[r] = *(const float4*)(Vg + (size_t)(kbase + kc + kk) * (NKV * HD) + d4);
      }
      __syncthreads();
#pragma unroll
      for (int r = 0; r < 2; r++) {
        int idx = r * 256 + tid;
        int kk = idx >> 5, d4 = (idx & 31) * 4;
        Vs[kk][d4] = vv[r].x; Vs[kk][d4 + 1] = vv[r].y;
        Vs[kk][d4 + 2] = vv[r].z; Vs[kk][d4 + 3] = vv[r].w;
      }
      __syncthreads();
#pragma unroll
      for (int kk = 0; kk < 16; kk++) {
        float p0 = Ps[ty * 2][kc + kk];
        float p1 = Ps[ty * 2 + 1][kc + kk];
        float4 v0 = *(const float4*)&Vs[kk][tx * 8];
        float4 v1 = *(const float4*)&Vs[kk][tx * 8 + 4];
        o[0][0] += p0 * v0.x; o[0][1] += p0 * v0.y; o[0][2] += p0 * v0.z; o[0][3] += p0 * v0.w;
        o[0][4] += p0 * v1.x; o[0][5] += p0 * v1.y; o[0][6] += p0 * v1.z; o[0][7] += p0 * v1.w;
        o[1][0] += p1 * v0.x; o[1][1] += p1 * v0.y; o[1][2] += p1 * v0.z; o[1][3] += p1 * v0.w;
        o[1][4] += p1 * v1.x; o[1][5] += p1 * v1.y; o[1][6] += p1 * v1.z; o[1][7] += p1 * v1.w;
      }
      __syncthreads();
    }
  }
#pragma unroll
  for (int i = 0; i < 2; i++) {
    float rl = 1.0f / l_i[i];
    float* Orow = O + (size_t)(qbase + ty * 2 + i) * (NH * HD) + h * HD + tx * 8;
    *(float4*)(Orow)     = make_float4(o[i][0] * rl, o[i][1] * rl, o[i][2] * rl, o[i][3] * rl);
    *(float4*)(Orow + 4) = make_float4(o[i][4] * rl, o[i][5] * rl, o[i][6] * rl, o[i][7] * rl);
  }
}

// ---------------------------------------------------------------------------
// Host launcher
// ---------------------------------------------------------------------------
extern "C" void kernel_launch(void* const* d_in, const int* in_sizes, int n_in,
                              void* d_out, int out_size) {
  const float* hidden = (const float*)d_in[0];
  const float* Wq = (const float*)d_in[1];
  const float* Wk = (const float*)d_in[2];
  const float* Wv = (const float*)d_in[3];
  const float* Wo = (const float*)d_in[4];
  const float* cosp = (const float*)d_in[5];
  const float* sinp = (const float*)d_in[6];
  const int* qcol = (const int*)d_in[8];
  const int* qrow = (const int*)d_in[9];
  const int* kcol = (const int*)d_in[10];
  const int* krow = (const int*)d_in[11];
  const int* vcol = (const int*)d_in[12];
  const int* vrow = (const int*)d_in[13];
  const int* ocol = (const int*)d_in[14];
  const int* orow = (const int*)d_in[15];

  __nv_bfloat16 *hqh, *hql, *hkh, *hkl, *hvh, *hvl, *aoh, *aol;
  __nv_bfloat16 *wqh, *wql, *wkh, *wkl, *wvh, *wvl, *woh, *wol;
  float *Qb, *Kb, *Vb, *Ab;
  cudaGetSymbolAddress((void**)&hqh, g_hq_h); cudaGetSymbolAddress((void**)&hql, g_hq_l);
  cudaGetSymbolAddress((void**)&hkh, g_hk_h); cudaGetSymbolAddress((void**)&hkl, g_hk_l);
  cudaGetSymbolAddress((void**)&hvh, g_hv_h); cudaGetSymbolAddress((void**)&hvl, g_hv_l);
  cudaGetSymbolAddress((void**)&aoh, g_ao_h); cudaGetSymbolAddress((void**)&aol, g_ao_l);
  cudaGetSymbolAddress((void**)&wqh, g_wq_h); cudaGetSymbolAddress((void**)&wql, g_wq_l);
  cudaGetSymbolAddress((void**)&wkh, g_wk_h); cudaGetSymbolAddress((void**)&wkl, g_wk_l);
  cudaGetSymbolAddress((void**)&wvh, g_wv_h); cudaGetSymbolAddress((void**)&wvl, g_wv_l);
  cudaGetSymbolAddress((void**)&woh, g_wo_h); cudaGetSymbolAddress((void**)&wol, g_wo_l);
  cudaGetSymbolAddress((void**)&Qb, g_Q);
  cudaGetSymbolAddress((void**)&Kb, g_K);
  cudaGetSymbolAddress((void**)&Vb, g_V);
  cudaGetSymbolAddress((void**)&Ab, g_A);

  cudaFuncSetAttribute(gemm_mma_kernel,
                       cudaFuncAttributeMaxDynamicSharedMemorySize, GEMM_SMEM);

  dim3 gth(HDIM / 256, SEQ);
  gather_convert_kernel<<<gth, 256>>>(hidden, qcol, hqh, hql);
  gather_convert_kernel<<<gth, 256>>>(hidden, kcol, hkh, hkl);
  gather_convert_kernel<<<gth, 256>>>(hidden, vcol, hvh, hvl);

  wconvert_kernel<<<dim3(16, 4096), 256>>>(Wq, qrow, wqh, wql);
  wconvert_kernel<<<dim3(16, 1024), 256>>>(Wk, krow, wkh, wkl);
  wconvert_kernel<<<dim3(16, 1024), 256>>>(Wv, vrow, wvh, wvl);
  wconvert_kernel<<<dim3(16, 4096), 256>>>(Wo, orow, woh, wol);

  gemm_mma_kernel<<<dim3(16, 32), 256, GEMM_SMEM>>>(hqh, hql, wqh, wql, Qb, 4096);
  gemm_mma_kernel<<<dim3(16, 8),  256, GEMM_SMEM>>>(hkh, hkl, wkh, wkl, Kb, 1024);
  gemm_mma_kernel<<<dim3(16, 8),  256, GEMM_SMEM>>>(hvh, hvl, wvh, wvl, Vb, 1024);

  rope_kernel<<<(SEQ * NH * 64) / 256, 256>>>(Qb, cosp, sinp, NH);
  rope_kernel<<<(SEQ * NKV * 64) / 256, 256>>>(Kb, cosp, sinp, NKV);

  flash_kernel<<<dim3(SEQ / 32, NH), 256>>>(Qb, Kb, Vb, Ab);

  gather_convert_kernel<<<gth, 256>>>(Ab, ocol, aoh, aol);
  gemm_mma_kernel<<<dim3(16, 32), 256, GEMM_SMEM>>>(aoh, aol, woh, wol, (float*)d_out, 4096);
}

// round 7
// speedup vs baseline: 3.3158x; 2.9196x over previous
#include <cuda_runtime.h>
#include <cuda_bf16.h>
#include <cstdint>

#define SEQ   2048
#define HDIM  4096
#define NH    32
#define NKV   8
#define HD    128

// ---------------------------------------------------------------------------
// Scratch (__device__ globals; no cudaMalloc allowed)
// ---------------------------------------------------------------------------
__device__ __nv_bfloat16 g_hq_h[SEQ * HDIM], g_hq_l[SEQ * HDIM];
__device__ __nv_bfloat16 g_hk_h[SEQ * HDIM], g_hk_l[SEQ * HDIM];
__device__ __nv_bfloat16 g_hv_h[SEQ * HDIM], g_hv_l[SEQ * HDIM];
__device__ __nv_bfloat16 g_ao_h[SEQ * HDIM], g_ao_l[SEQ * HDIM];
__device__ __nv_bfloat16 g_wq_h[4096 * 4096], g_wq_l[4096 * 4096];
__device__ __nv_bfloat16 g_wk_h[1024 * 4096], g_wk_l[1024 * 4096];
__device__ __nv_bfloat16 g_wv_h[1024 * 4096], g_wv_l[1024 * 4096];
__device__ __nv_bfloat16 g_wo_h[4096 * 4096], g_wo_l[4096 * 4096];
__device__ float g_Q[SEQ * NH * HD];
__device__ float g_K[SEQ * NKV * HD];
__device__ float g_V[SEQ * NKV * HD];
__device__ float g_A[SEQ * NH * HD];
__device__ __nv_bfloat16 g_Qbf[SEQ * NH * HD];
__device__ __nv_bfloat16 g_Kbf[SEQ * NKV * HD];
__device__ __nv_bfloat16 g_Vhb[SEQ * NKV * HD];
__device__ __nv_bfloat16 g_Vlb[SEQ * NKV * HD];

// ---------------------------------------------------------------------------
// PTX helpers (baseline PTX only; works on plain sm_103 target)
// ---------------------------------------------------------------------------
static __device__ __forceinline__ uint32_t smem_u32(const void* p) {
  uint32_t a;
  asm("{ .reg .u64 t; cvta.to.shared.u64 t, %1; cvt.u32.u64 %0, t; }"
      : "=r"(a) : "l"(p));
  return a;
}

#define CP_ASYNC16(dst, src) \
  asm volatile("cp.async.cg.shared.global [%0], [%1], 16;" :: "r"(dst), "l"(src))
#define CP_COMMIT()   asm volatile("cp.async.commit_group;" ::: "memory")
#define CP_WAIT(n)    asm volatile("cp.async.wait_group %0;" :: "n"(n) : "memory")

static __device__ __forceinline__ void ldsm_x4(uint32_t* r, uint32_t addr) {
  asm volatile("ldmatrix.sync.aligned.m8n8.x4.shared.b16 {%0,%1,%2,%3}, [%4];"
               : "=r"(r[0]), "=r"(r[1]), "=r"(r[2]), "=r"(r[3]) : "r"(addr));
}
static __device__ __forceinline__ void ldsm_x4_t(uint32_t* r, uint32_t addr) {
  asm volatile("ldmatrix.sync.aligned.m8n8.x4.trans.shared.b16 {%0,%1,%2,%3}, [%4];"
               : "=r"(r[0]), "=r"(r[1]), "=r"(r[2]), "=r"(r[3]) : "r"(addr));
}

static __device__ __forceinline__ void mma_bf16(float* d, const uint32_t* a,
                                                const uint32_t* b) {
  asm volatile(
      "mma.sync.aligned.m16n8k16.row.col.f32.bf16.bf16.f32 "
      "{%0,%1,%2,%3}, {%4,%5,%6,%7}, {%8,%9}, {%0,%1,%2,%3};"
      : "+f"(d[0]), "+f"(d[1]), "+f"(d[2]), "+f"(d[3])
      : "r"(a[0]), "r"(a[1]), "r"(a[2]), "r"(a[3]), "r"(b[0]), "r"(b[1]));
}

static __device__ __forceinline__ uint32_t pkbf(float a, float b) {
  __nv_bfloat162 t = __floats2bfloat162_rn(a, b);  // x=a (low), y=b (high)
  return *(uint32_t*)&t;
}

// ---------------------------------------------------------------------------
// Conversion kernels (fold column/row permutations into fp32 -> bf16 hi/lo)
// ---------------------------------------------------------------------------
__global__ void __launch_bounds__(256) gather_convert_kernel(
    const float* __restrict__ in, const int* __restrict__ idx,
    __nv_bfloat16* __restrict__ oh, __nv_bfloat16* __restrict__ ol) {
  int t = blockIdx.y;
  int c = blockIdx.x * 256 + threadIdx.x;
  float v = in[(size_t)t * HDIM + idx[c]];
  __nv_bfloat16 h = __float2bfloat16(v);
  oh[(size_t)t * HDIM + c] = h;
  ol[(size_t)t * HDIM + c] = __float2bfloat16(v - __bfloat162float(h));
}

__global__ void __launch_bounds__(256) wconvert_kernel(
    const float* __restrict__ W, const int* __restrict__ ridx,
    __nv_bfloat16* __restrict__ oh, __nv_bfloat16* __restrict__ ol) {
  int j = blockIdx.y;
  int c = blockIdx.x * 256 + threadIdx.x;
  float v = W[(size_t)ridx[j] * HDIM + c];
  __nv_bfloat16 h = __float2bfloat16(v);
  oh[(size_t)j * HDIM + c] = h;
  ol[(size_t)j * HDIM + c] = __float2bfloat16(v - __bfloat162float(h));
}

// V split: fp32 -> bf16 hi + lo
__global__ void __launch_bounds__(256) vsplit_kernel(
    const float* __restrict__ in, __nv_bfloat16* __restrict__ oh,
    __nv_bfloat16* __restrict__ ol) {
  size_t i = (size_t)blockIdx.x * 256 + threadIdx.x;
  float v = in[i];
  __nv_bfloat16 h = __float2bfloat16(v);
  oh[i] = h;
  ol[i] = __float2bfloat16(v - __bfloat162float(h));
}

// ---------------------------------------------------------------------------
// Split-bf16 tensor-core GEMM via mma.sync (unchanged from passing round 6)
// ---------------------------------------------------------------------------
#define STAGE_B 40960
#define GEMM_SMEM (2 * STAGE_B)

__global__ void __launch_bounds__(256, 1) gemm_mma_kernel(
    const __nv_bfloat16* __restrict__ Ah, const __nv_bfloat16* __restrict__ Al,
    const __nv_bfloat16* __restrict__ Bh, const __nv_bfloat16* __restrict__ Bl,
    float* __restrict__ C, int Ntot) {
  extern __shared__ __align__(1024) char smem[];
  uint32_t sb = smem_u32(smem);
  const int tid = threadIdx.x, wid = tid >> 5, lane = tid & 31;
  const int row0 = blockIdx.x * 128, col0 = blockIdx.y * 128;

  const __nv_bfloat16* ld_src[8];
  uint32_t ld_dst[8];
#pragma unroll
  for (int i = 0; i < 8; i++) {
    int t = i * 256 + tid;
    int mat = t >> 9, r = (t >> 2) & 127, c = t & 3;
    const __nv_bfloat16* base =
        (mat == 0) ? Ah + (size_t)row0 * 4096 :
        (mat == 1) ? Al + (size_t)row0 * 4096 :
        (mat == 2) ? Bh + (size_t)col0 * 4096 :
                     Bl + (size_t)col0 * 4096;
    ld_src[i] = base + (size_t)r * 4096 + c * 8;
    ld_dst[i] = (uint32_t)(mat * 10240 + r * 80 + c * 16);
  }

  const int m0 = (wid & 3) * 32, n0 = (wid >> 2) * 64;
  const uint32_t a_lrow = (lane & 7) + ((lane >> 3) & 1) * 8;
  const uint32_t a_lk   = ((lane >> 4) & 1) * 8;
  const uint32_t b_lrow = (lane & 7) + ((lane >> 4) & 1) * 8;
  const uint32_t b_lk   = ((lane >> 3) & 1) * 8;

  float acc[2][8][4];
#pragma unroll
  for (int mt = 0; mt < 2; mt++)
#pragma unroll
    for (int nt = 0; nt < 8; nt++)
#pragma unroll
      for (int j = 0; j < 4; j++) acc[mt][nt][j] = 0.f;

#pragma unroll
  for (int i = 0; i < 8; i++) CP_ASYNC16(sb + ld_dst[i], ld_src[i]);
  CP_COMMIT();

#pragma unroll 1
  for (int kc = 0; kc < 128; kc++) {
    const int p = kc & 1;
    if (kc + 1 < 128) {
      const uint32_t qb = sb + (p ^ 1) * STAGE_B;
      const int ko = (kc + 1) * 32;
#pragma unroll
      for (int i = 0; i < 8; i++) CP_ASYNC16(qb + ld_dst[i], ld_src[i] + ko);
      CP_COMMIT();
      CP_WAIT(1);
    } else {
      CP_WAIT(0);
    }
    __syncthreads();

    const uint32_t base = sb + p * STAGE_B;
#pragma unroll
    for (int ks = 0; ks < 32; ks += 16) {
      uint32_t ah[2][4], al[2][4];
#pragma unroll
      for (int mt = 0; mt < 2; mt++) {
        uint32_t ro = (m0 + mt * 16 + a_lrow) * 80 + (ks + a_lk) * 2;
        ldsm_x4(ah[mt], base + ro);
        ldsm_x4(al[mt], base + 10240 + ro);
      }
      uint32_t bh[8][2], bl[8][2];
#pragma unroll
      for (int nt2 = 0; nt2 < 4; nt2++) {
        uint32_t ro = (n0 + nt2 * 16 + b_lrow) * 80 + (ks + b_lk) * 2;
        uint32_t t0[4], t1[4];
        ldsm_x4(t0, base + 20480 + ro);
        ldsm_x4(t1, base + 30720 + ro);
        bh[nt2 * 2][0] = t0[0]; bh[nt2 * 2][1] = t0[1];
        bh[nt2 * 2 + 1][0] = t0[2]; bh[nt2 * 2 + 1][1] = t0[3];
        bl[nt2 * 2][0] = t1[0]; bl[nt2 * 2][1] = t1[1];
        bl[nt2 * 2 + 1][0] = t1[2]; bl[nt2 * 2 + 1][1] = t1[3];
      }
#pragma unroll
      for (int mt = 0; mt < 2; mt++)
#pragma unroll
        for (int nt = 0; nt < 8; nt++) {
          mma_bf16(acc[mt][nt], ah[mt], bh[nt]);
          mma_bf16(acc[mt][nt], ah[mt], bl[nt]);
          mma_bf16(acc[mt][nt], al[mt], bh[nt]);
        }
    }
    __syncthreads();
  }

#pragma unroll
  for (int mt = 0; mt < 2; mt++)
#pragma unroll
    for (int nt = 0; nt < 8; nt++) {
      int m = row0 + m0 + mt * 16 + (lane >> 2);
      int n = col0 + n0 + nt * 8 + (lane & 3) * 2;
      *(float2*)&C[(size_t)m * Ntot + n] =
          make_float2(acc[mt][nt][0], acc[mt][nt][1]);
      *(float2*)&C[(size_t)(m + 8) * Ntot + n] =
          make_float2(acc[mt][nt][2], acc[mt][nt][3]);
    }
}

// ---------------------------------------------------------------------------
// RoPE: fp32 in -> bf16 out
// ---------------------------------------------------------------------------
__global__ void __launch_bounds__(256) rope_bf16_kernel(
    const float* __restrict__ x, const float* __restrict__ cs,
    const float* __restrict__ sn, __nv_bfloat16* __restrict__ out, int nheads) {
  int idx = blockIdx.x * 256 + threadIdx.x;
  int d = idx & 63;
  int h = (idx >> 6) % nheads;
  int t = idx / (64 * nheads);
  float c1 = cs[t * 128 + d],      s1 = sn[t * 128 + d];
  float c2 = cs[t * 128 + d + 64], s2 = sn[t * 128 + d + 64];
  const float* row = x + (size_t)t * (nheads * 128) + h * 128;
  __nv_bfloat16* orow = out + (size_t)t * (nheads * 128) + h * 128;
  float x1 = row[d], x2 = row[d + 64];
  orow[d]      = __float2bfloat16(x1 * c1 - x2 * s1);
  orow[d + 64] = __float2bfloat16(x2 * c2 + x1 * s2);
}

// ---------------------------------------------------------------------------
// Flash attention with mma.sync bf16.
// BM=64 q-rows, BN=64 keys, HD=128. 4 warps; warp w owns q-rows [16w,16w+16).
// S = Qh*Kh (single bf16 pass; scores tiny -> abs err ~1e-5).
// PV = Ph*Vh + Ph*Vl + Pl*Vh (split P from fp32 frags, split V precomputed).
// ---------------------------------------------------------------------------
#define FP 136   // smem pitch (bf16 elems): 272B/row, conflict-free ldmatrix
#define FLASH_SMEM (4 * 64 * FP * 2)

__global__ void __launch_bounds__(128) flash_mma_kernel(
    const __nv_bfloat16* __restrict__ Qbf, const __nv_bfloat16* __restrict__ Kbf,
    const __nv_bfloat16* __restrict__ Vh, const __nv_bfloat16* __restrict__ Vl,
    float* __restrict__ O) {
  extern __shared__ __align__(1024) char smem[];
  __nv_bfloat16* Qs  = (__nv_bfloat16*)smem;
  __nv_bfloat16* Ks  = Qs + 64 * FP;
  __nv_bfloat16* Vhs = Qs + 2 * 64 * FP;
  __nv_bfloat16* Vls = Qs + 3 * 64 * FP;

  const int h = blockIdx.y, kvh = h >> 2;
  const int qt = blockIdx.x, qbase = qt * 64;
  const int tid = threadIdx.x, w = tid >> 5, lane = tid & 31;
  const float scale = 0.08838834764831845f;  // 1/sqrt(128)

  // Load Q tile (64 x 128 bf16)
#pragma unroll
  for (int i = 0; i < 8; i++) {
    int idx = i * 128 + tid;
    int r = idx >> 4, c = idx & 15;
    *(float4*)&Qs[r * FP + c * 8] =
        *(const float4*)&Qbf[(size_t)(qbase + r) * (NH * HD) + h * HD + c * 8];
  }
  __syncthreads();

  // Preload Q A-fragments for all 8 k-steps (d dimension)
  const uint32_t a_lrow = (lane & 7) + ((lane >> 3) & 1) * 8;
  const uint32_t a_lk   = ((lane >> 4) & 1) * 8;
  const uint32_t b_lrow = (lane & 7) + ((lane >> 4) & 1) * 8;
  const uint32_t b_lk   = ((lane >> 3) & 1) * 8;
  uint32_t qa[8][4];
  {
    uint32_t qsb = smem_u32(Qs);
#pragma unroll
    for (int ks = 0; ks < 8; ks++)
      ldsm_x4(qa[ks], qsb + ((w * 16 + a_lrow) * FP + ks * 16 + a_lk) * 2);
  }

  const int row0 = qbase + w * 16 + (lane >> 2);
  const int row1 = row0 + 8;

  float m_i[2] = {-1e30f, -1e30f}, l_i[2] = {0.f, 0.f};
  float o[16][4];
#pragma unroll
  for (int nt = 0; nt < 16; nt++)
#pragma unroll
    for (int j = 0; j < 4; j++) o[nt][j] = 0.f;

  const uint32_t ksb = smem_u32(Ks), vhb = smem_u32(Vhs), vlb = smem_u32(Vls);

#pragma unroll 1
  for (int kt = 0; kt <= qt; kt++) {
    const int kbase = kt * 64;
    __syncthreads();  // previous iter's frag reads done
#pragma unroll
    for (int i = 0; i < 8; i++) {
      int idx = i * 128 + tid;
      int r = idx >> 4, c = idx & 15;
      size_t g = (size_t)(kbase + r) * (NKV * HD) + kvh * HD + c * 8;
      *(float4*)&Ks[r * FP + c * 8]  = *(const float4*)&Kbf[g];
      *(float4*)&Vhs[r * FP + c * 8] = *(const float4*)&Vh[g];
      *(float4*)&Vls[r * FP + c * 8] = *(const float4*)&Vl[g];
    }
    __syncthreads();

    // S = Q K^T  (8 key-ntiles x 4 fp32)
    float s[8][4];
#pragma unroll
    for (int nt = 0; nt < 8; nt++)
#pragma unroll
      for (int j = 0; j < 4; j++) s[nt][j] = 0.f;
#pragma unroll
    for (int np = 0; np < 4; np++) {
#pragma unroll
      for (int ks = 0; ks < 8; ks++) {
        uint32_t kb[4];
        ldsm_x4(kb, ksb + ((np * 16 + b_lrow) * FP + ks * 16 + b_lk) * 2);
        mma_bf16(s[np * 2],     qa[ks], kb);
        mma_bf16(s[np * 2 + 1], qa[ks], kb + 2);
      }
    }

    // Softmax (rows r=lane>>2 and r+8; cols shared by 4-lane quads)
    float rm0 = -1e30f, rm1 = -1e30f;
    const bool diag = (kt == qt);
#pragma unroll
    for (int nt = 0; nt < 8; nt++) {
      int c0 = kbase + nt * 8 + (lane & 3) * 2;
#pragma unroll
      for (int j = 0; j < 4; j++) s[nt][j] *= scale;
      if (diag) {
        if (c0     > row0) s[nt][0] = -1e30f;
        if (c0 + 1 > row0) s[nt][1] = -1e30f;
        if (c0     > row1) s[nt][2] = -1e30f;
        if (c0 + 1 > row1) s[nt][3] = -1e30f;
      }
      rm0 = fmaxf(rm0, fmaxf(s[nt][0], s[nt][1]));
      rm1 = fmaxf(rm1, fmaxf(s[nt][2], s[nt][3]));
    }
#pragma unroll
    for (int off = 1; off <= 2; off <<= 1) {
      rm0 = fmaxf(rm0, __shfl_xor_sync(0xffffffffu, rm0, off));
      rm1 = fmaxf(rm1, __shfl_xor_sync(0xffffffffu, rm1, off));
    }
    float mn0 = fmaxf(m_i[0], rm0), mn1 = fmaxf(m_i[1], rm1);
    float cor0 = __expf(m_i[0] - mn0), cor1 = __expf(m_i[1] - mn1);
    float rs0 = 0.f, rs1 = 0.f;
#pragma unroll
    for (int nt = 0; nt < 8; nt++) {
      s[nt][0] = __expf(s[nt][0] - mn0); rs0 += s[nt][0];
      s[nt][1] = __expf(s[nt][1] - mn0); rs0 += s[nt][1];
      s[nt][2] = __expf(s[nt][2] - mn1); rs1 += s[nt][2];
      s[nt][3] = __expf(s[nt][3] - mn1); rs1 += s[nt][3];
    }
#pragma unroll
    for (int off = 1; off <= 2; off <<= 1) {
      rs0 += __shfl_xor_sync(0xffffffffu, rs0, off);
      rs1 += __shfl_xor_sync(0xffffffffu, rs1, off);
    }
    l_i[0] = l_i[0] * cor0 + rs0; m_i[0] = mn0;
    l_i[1] = l_i[1] * cor1 + rs1; m_i[1] = mn1;
#pragma unroll
    for (int nt = 0; nt < 16; nt++) {
      o[nt][0] *= cor0; o[nt][1] *= cor0;
      o[nt][2] *= cor1; o[nt][3] *= cor1;
    }

    // PV: 4 k-steps of 16 keys; P split hi/lo in-register
#pragma unroll
    for (int kk = 0; kk < 4; kk++) {
      float* p0 = s[kk * 2];      // keys 16kk+0..7
      float* p1 = s[kk * 2 + 1];  // keys 16kk+8..15
      uint32_t ph[4], pl[4];
      ph[0] = pkbf(p0[0], p0[1]); ph[1] = pkbf(p0[2], p0[3]);
      ph[2] = pkbf(p1[0], p1[1]); ph[3] = pkbf(p1[2], p1[3]);
      float q00 = p0[0] - __bfloat162float(__float2bfloat16(p0[0]));
      float q01 = p0[1] - __bfloat162float(__float2bfloat16(p0[1]));
      float q02 = p0[2] - __bfloat162float(__float2bfloat16(p0[2]));
      float q03 = p0[3] - __bfloat162float(__float2bfloat16(p0[3]));
      float q10 = p1[0] - __bfloat162float(__float2bfloat16(p1[0]));
      float q11 = p1[1] - __bfloat162float(__float2bfloat16(p1[1]));
      float q12 = p1[2] - __bfloat162float(__float2bfloat16(p1[2]));
      float q13 = p1[3] - __bfloat162float(__float2bfloat16(p1[3]));
      pl[0] = pkbf(q00, q01); pl[1] = pkbf(q02, q03);
      pl[2] = pkbf(q10, q11); pl[3] = pkbf(q12, q13);

      uint32_t vro = ((kk * 16 + (lane & 15)) * FP + ((lane >> 4) << 3)) * 2;
#pragma unroll
      for (int ntp = 0; ntp < 8; ntp++) {
        uint32_t vh4[4], vl4[4];
        ldsm_x4_t(vh4, vhb + vro + ntp * 32);
        ldsm_x4_t(vl4, vlb + vro + ntp * 32);
        mma_bf16(o[ntp * 2],     ph, vh4);
        mma_bf16(o[ntp * 2 + 1], ph, vh4 + 2);
        mma_bf16(o[ntp * 2],     ph, vl4);
        mma_bf16(o[ntp * 2 + 1], ph, vl4 + 2);
        mma_bf16(o[ntp * 2],     pl, vh4);
        mma_bf16(o[ntp * 2 + 1], pl, vh4 + 2);
      }
    }
  }

  // Epilogue
  float rl0 = 1.0f / l_i[0], rl1 = 1.0f / l_i[1];
#pragma unroll
  for (int nt = 0; nt < 16; nt++) {
    int col = h * HD + nt * 8 + (lane & 3) * 2;
    *(float2*)&O[(size_t)row0 * (NH * HD) + col] =
        make_float2(o[nt][0] * rl0, o[nt][1] * rl0);
    *(float2*)&O[(size_t)row1 * (NH * HD) + col] =
        make_float2(o[nt][2] * rl1, o[nt][3] * rl1);
  }
}

// ---------------------------------------------------------------------------
// Host launcher
// ---------------------------------------------------------------------------
extern "C" void kernel_launch(void* const* d_in, const int* in_sizes, int n_in,
                              void* d_out, int out_size) {
  const float* hidden = (const float*)d_in[0];
  const float* Wq = (const float*)d_in[1];
  const float* Wk = (const float*)d_in[2];
  const float* Wv = (const float*)d_in[3];
  const float* Wo = (const float*)d_in[4];
  const float* cosp = (const float*)d_in[5];
  const float* sinp = (const float*)d_in[6];
  const int* qcol = (const int*)d_in[8];
  const int* qrow = (const int*)d_in[9];
  const int* kcol = (const int*)d_in[10];
  const int* krow = (const int*)d_in[11];
  const int* vcol = (const int*)d_in[12];
  const int* vrow = (const int*)d_in[13];
  const int* ocol = (const int*)d_in[14];
  const int* orow = (const int*)d_in[15];

  __nv_bfloat16 *hqh, *hql, *hkh, *hkl, *hvh, *hvl, *aoh, *aol;
  __nv_bfloat16 *wqh, *wql, *wkh, *wkl, *wvh, *wvl, *woh, *wol;
  __nv_bfloat16 *Qbf, *Kbf, *Vhb, *Vlb;
  float *Qb, *Kb, *Vb, *Ab;
  cudaGetSymbolAddress((void**)&hqh, g_hq_h); cudaGetSymbolAddress((void**)&hql, g_hq_l);
  cudaGetSymbolAddress((void**)&hkh, g_hk_h); cudaGetSymbolAddress((void**)&hkl, g_hk_l);
  cudaGetSymbolAddress((void**)&hvh, g_hv_h); cudaGetSymbolAddress((void**)&hvl, g_hv_l);
  cudaGetSymbolAddress((void**)&aoh, g_ao_h); cudaGetSymbolAddress((void**)&aol, g_ao_l);
  cudaGetSymbolAddress((void**)&wqh, g_wq_h); cudaGetSymbolAddress((void**)&wql, g_wq_l);
  cudaGetSymbolAddress((void**)&wkh, g_wk_h); cudaGetSymbolAddress((void**)&wkl, g_wk_l);
  cudaGetSymbolAddress((void**)&wvh, g_wv_h); cudaGetSymbolAddress((void**)&wvl, g_wv_l);
  cudaGetSymbolAddress((void**)&woh, g_wo_h); cudaGetSymbolAddress((void**)&wol, g_wo_l);
  cudaGetSymbolAddress((void**)&Qb, g_Q);
  cudaGetSymbolAddress((void**)&Kb, g_K);
  cudaGetSymbolAddress((void**)&Vb, g_V);
  cudaGetSymbolAddress((void**)&Ab, g_A);
  cudaGetSymbolAddress((void**)&Qbf, g_Qbf);
  cudaGetSymbolAddress((void**)&Kbf, g_Kbf);
  cudaGetSymbolAddress((void**)&Vhb, g_Vhb);
  cudaGetSymbolAddress((void**)&Vlb, g_Vlb);

  cudaFuncSetAttribute(gemm_mma_kernel,
                       cudaFuncAttributeMaxDynamicSharedMemorySize, GEMM_SMEM);
  cudaFuncSetAttribute(flash_mma_kernel,
                       cudaFuncAttributeMaxDynamicSharedMemorySize, FLASH_SMEM);

  dim3 gth(HDIM / 256, SEQ);
  gather_convert_kernel<<<gth, 256>>>(hidden, qcol, hqh, hql);
  gather_convert_kernel<<<gth, 256>>>(hidden, kcol, hkh, hkl);
  gather_convert_kernel<<<gth, 256>>>(hidden, vcol, hvh, hvl);

  wconvert_kernel<<<dim3(16, 4096), 256>>>(Wq, qrow, wqh, wql);
  wconvert_kernel<<<dim3(16, 1024), 256>>>(Wk, krow, wkh, wkl);
  wconvert_kernel<<<dim3(16, 1024), 256>>>(Wv, vrow, wvh, wvl);
  wconvert_kernel<<<dim3(16, 4096), 256>>>(Wo, orow, woh, wol);

  gemm_mma_kernel<<<dim3(16, 32), 256, GEMM_SMEM>>>(hqh, hql, wqh, wql, Qb, 4096);
  gemm_mma_kernel<<<dim3(16, 8),  256, GEMM_SMEM>>>(hkh, hkl, wkh, wkl, Kb, 1024);
  gemm_mma_kernel<<<dim3(16, 8),  256, GEMM_SMEM>>>(hvh, hvl, wvh, wvl, Vb, 1024);

  rope_bf16_kernel<<<(SEQ * NH * 64) / 256, 256>>>(Qb, cosp, sinp, Qbf, NH);
  rope_bf16_kernel<<<(SEQ * NKV * 64) / 256, 256>>>(Kb, cosp, sinp, Kbf, NKV);
  vsplit_kernel<<<(SEQ * NKV * HD) / 256, 256>>>(Vb, Vhb, Vlb);

  flash_mma_kernel<<<dim3(SEQ / 64, NH), 128, FLASH_SMEM>>>(Qbf, Kbf, Vhb, Vlb, Ab);

  gather_convert_kernel<<<gth, 256>>>(Ab, ocol, aoh, aol);
  gemm_mma_kernel<<<dim3(16, 32), 256, GEMM_SMEM>>>(aoh, aol, woh, wol, (float*)d_out, 4096);
}

// round 9
// speedup vs baseline: 3.5753x; 1.0783x over previous
#include <cuda_runtime.h>
#include <cuda_bf16.h>
#include <cstdint>

#define SEQ   2048
#define HDIM  4096
#define NH    32
#define NKV   8
#define HD    128

// ---------------------------------------------------------------------------
// Scratch (__device__ globals; no cudaMalloc allowed)
// ---------------------------------------------------------------------------
__device__ __nv_bfloat16 g_hq_h[SEQ * HDIM], g_hq_l[SEQ * HDIM];
__device__ __nv_bfloat16 g_hk_h[SEQ * HDIM], g_hk_l[SEQ * HDIM];
__device__ __nv_bfloat16 g_hv_h[SEQ * HDIM], g_hv_l[SEQ * HDIM];
__device__ __nv_bfloat16 g_ao_h[SEQ * HDIM], g_ao_l[SEQ * HDIM];
__device__ __nv_bfloat16 g_wq_h[4096 * 4096], g_wq_l[4096 * 4096];
__device__ __nv_bfloat16 g_wk_h[1024 * 4096], g_wk_l[1024 * 4096];
__device__ __nv_bfloat16 g_wv_h[1024 * 4096], g_wv_l[1024 * 4096];
__device__ __nv_bfloat16 g_wo_h[4096 * 4096], g_wo_l[4096 * 4096];
__device__ float g_Q[SEQ * NH * HD];
__device__ float g_K[SEQ * NKV * HD];
__device__ float g_V[SEQ * NKV * HD];
__device__ float g_A[SEQ * NH * HD];
__device__ __nv_bfloat16 g_Qbf[SEQ * NH * HD];
__device__ __nv_bfloat16 g_Kbf[SEQ * NKV * HD];
__device__ __nv_bfloat16 g_Vhb[SEQ * NKV * HD];
__device__ __nv_bfloat16 g_Vlb[SEQ * NKV * HD];

// ---------------------------------------------------------------------------
// PTX helpers (baseline PTX only; works on plain sm_103 target)
// ---------------------------------------------------------------------------
static __device__ __forceinline__ uint32_t smem_u32(const void* p) {
  uint32_t a;
  asm("{ .reg .u64 t; cvta.to.shared.u64 t, %1; cvt.u32.u64 %0, t; }"
      : "=r"(a) : "l"(p));
  return a;
}

#define CP_ASYNC16(dst, src) \
  asm volatile("cp.async.cg.shared.global [%0], [%1], 16;" :: "r"(dst), "l"(src))
#define CP_COMMIT()   asm volatile("cp.async.commit_group;" ::: "memory")
#define CP_WAIT(n)    asm volatile("cp.async.wait_group %0;" :: "n"(n) : "memory")

static __device__ __forceinline__ void ldsm_x4(uint32_t* r, uint32_t addr) {
  asm volatile("ldmatrix.sync.aligned.m8n8.x4.shared.b16 {%0,%1,%2,%3}, [%4];"
               : "=r"(r[0]), "=r"(r[1]), "=r"(r[2]), "=r"(r[3]) : "r"(addr));
}
static __device__ __forceinline__ void ldsm_x4_t(uint32_t* r, uint32_t addr) {
  asm volatile("ldmatrix.sync.aligned.m8n8.x4.trans.shared.b16 {%0,%1,%2,%3}, [%4];"
               : "=r"(r[0]), "=r"(r[1]), "=r"(r[2]), "=r"(r[3]) : "r"(addr));
}

static __device__ __forceinline__ void mma_bf16(float* d, const uint32_t* a,
                                                const uint32_t* b) {
  asm volatile(
      "mma.sync.aligned.m16n8k16.row.col.f32.bf16.bf16.f32 "
      "{%0,%1,%2,%3}, {%4,%5,%6,%7}, {%8,%9}, {%0,%1,%2,%3};"
      : "+f"(d[0]), "+f"(d[1]), "+f"(d[2]), "+f"(d[3])
      : "r"(a[0]), "r"(a[1]), "r"(a[2]), "r"(a[3]), "r"(b[0]), "r"(b[1]));
}

static __device__ __forceinline__ uint32_t pkbf(float a, float b) {
  __nv_bfloat162 t = __floats2bfloat162_rn(a, b);
  return *(uint32_t*)&t;
}

// ---------------------------------------------------------------------------
// Fused 3-way gather+convert: per-row smem staging.
// Block = one row t; loads 16KB row coalesced, then 3 permuted hi/lo outputs.
// ---------------------------------------------------------------------------
__global__ void __launch_bounds__(256) gather3_convert_kernel(
    const float* __restrict__ in,
    const int* __restrict__ qi, const int* __restrict__ ki,
    const int* __restrict__ vi,
    __nv_bfloat16* __restrict__ qh, __nv_bfloat16* __restrict__ ql,
    __nv_bfloat16* __restrict__ kh, __nv_bfloat16* __restrict__ kl,
    __nv_bfloat16* __restrict__ vh, __nv_bfloat16* __restrict__ vl) {
  __shared__ __align__(16) float row[HDIM];
  const int t = blockIdx.x;
  const float* src = in + (size_t)t * HDIM;
#pragma unroll
  for (int i = 0; i < 4; i++) {
    int e = (i * 256 + threadIdx.x) * 4;
    *(float4*)&row[e] = *(const float4*)&src[e];
  }
  __syncthreads();
  const size_t base = (size_t)t * HDIM;
#pragma unroll
  for (int i = 0; i < 16; i++) {
    int c = i * 256 + threadIdx.x;
    float v0 = row[qi[c]];
    __nv_bfloat16 h0 = __float2bfloat16(v0);
    qh[base + c] = h0;
    ql[base + c] = __float2bfloat16(v0 - __bfloat162float(h0));
    float v1 = row[ki[c]];
    __nv_bfloat16 h1 = __float2bfloat16(v1);
    kh[base + c] = h1;
    kl[base + c] = __float2bfloat16(v1 - __bfloat162float(h1));
    float v2 = row[vi[c]];
    __nv_bfloat16 h2 = __float2bfloat16(v2);
    vh[base + c] = h2;
    vl[base + c] = __float2bfloat16(v2 - __bfloat162float(h2));
  }
}

// Single-perm variant (O path)
__global__ void __launch_bounds__(256) gather1_convert_kernel(
    const float* __restrict__ in, const int* __restrict__ idx,
    __nv_bfloat16* __restrict__ oh, __nv_bfloat16* __restrict__ ol) {
  __shared__ __align__(16) float row[HDIM];
  const int t = blockIdx.x;
  const float* src = in + (size_t)t * HDIM;
#pragma unroll
  for (int i = 0; i < 4; i++) {
    int e = (i * 256 + threadIdx.x) * 4;
    *(float4*)&row[e] = *(const float4*)&src[e];
  }
  __syncthreads();
  const size_t base = (size_t)t * HDIM;
#pragma unroll
  for (int i = 0; i < 16; i++) {
    int c = i * 256 + threadIdx.x;
    float v = row[idx[c]];
    __nv_bfloat16 h = __float2bfloat16(v);
    oh[base + c] = h;
    ol[base + c] = __float2bfloat16(v - __bfloat162float(h));
  }
}

// ---------------------------------------------------------------------------
// Vectorized weight convert: 4 elems/thread, float4 load, 8B packed stores.
// grid = (HDIM/1024, nrows)
// ---------------------------------------------------------------------------
__global__ void __launch_bounds__(256) wconvert_kernel(
    const float* __restrict__ W, const int* __restrict__ ridx,
    __nv_bfloat16* __restrict__ oh, __nv_bfloat16* __restrict__ ol) {
  int j = blockIdx.y;
  int c4 = (blockIdx.x * 256 + threadIdx.x) * 4;
  float4 v = *(const float4*)&W[(size_t)ridx[j] * HDIM + c4];
  __nv_bfloat16 h0 = __float2bfloat16(v.x), h1 = __float2bfloat16(v.y);
  __nv_bfloat16 h2 = __float2bfloat16(v.z), h3 = __float2bfloat16(v.w);
  uint2 hs, ls;
  hs.x = pkbf(v.x, v.y); hs.y = pkbf(v.z, v.w);  // pkbf rounds same as h0..h3
  ls.x = pkbf(v.x - __bfloat162float(h0), v.y - __bfloat162float(h1));
  ls.y = pkbf(v.z - __bfloat162float(h2), v.w - __bfloat162float(h3));
  *(uint2*)&oh[(size_t)j * HDIM + c4] = hs;
  *(uint2*)&ol[(size_t)j * HDIM + c4] = ls;
}

// ---------------------------------------------------------------------------
// Split-bf16 tensor-core GEMM via mma.sync.
// Mainloop identical to the passing round; added blockIdx.z pointer select
// so two independent GEMMs (K and V) can share one launch.
// ---------------------------------------------------------------------------
#define STAGE_B 40960
#define GEMM_SMEM (2 * STAGE_B)

__global__ void __launch_bounds__(256, 1) gemm_mma_kernel(
    const __nv_bfloat16* Ah_, const __nv_bfloat16* Al_,
    const __nv_bfloat16* Bh_, const __nv_bfloat16* Bl_,
    float* C_, int Ntot,
    const __nv_bfloat16* Ah2, const __nv_bfloat16* Al2,
    const __nv_bfloat16* Bh2, const __nv_bfloat16* Bl2, float* C2) {
  const __nv_bfloat16* Ah = Ah_; const __nv_bfloat16* Al = Al_;
  const __nv_bfloat16* Bh = Bh_; const __nv_bfloat16* Bl = Bl_;
  float* C = C_;
  if (blockIdx.z == 1) { Ah = Ah2; Al = Al2; Bh = Bh2; Bl = Bl2; C = C2; }

  extern __shared__ __align__(1024) char smem[];
  uint32_t sb = smem_u32(smem);
  const int tid = threadIdx.x, wid = tid >> 5, lane = tid & 31;
  const int row0 = blockIdx.x * 128, col0 = blockIdx.y * 128;

  const __nv_bfloat16* ld_src[8];
  uint32_t ld_dst[8];
#pragma unroll
  for (int i = 0; i < 8; i++) {
    int t = i * 256 + tid;
    int mat = t >> 9, r = (t >> 2) & 127, c = t & 3;
    const __nv_bfloat16* base =
        (mat == 0) ? Ah + (size_t)row0 * 4096 :
        (mat == 1) ? Al + (size_t)row0 * 4096 :
        (mat == 2) ? Bh + (size_t)col0 * 4096 :
                     Bl + (size_t)col0 * 4096;
    ld_src[i] = base + (size_t)r * 4096 + c * 8;
    ld_dst[i] = (uint32_t)(mat * 10240 + r * 80 + c * 16);
  }

  const int m0 = (wid & 3) * 32, n0 = (wid >> 2) * 64;
  const uint32_t a_lrow = (lane & 7) + ((lane >> 3) & 1) * 8;
  const uint32_t a_lk   = ((lane >> 4) & 1) * 8;
  const uint32_t b_lrow = (lane & 7) + ((lane >> 4) & 1) * 8;
  const uint32_t b_lk   = ((lane >> 3) & 1) * 8;

  float acc[2][8][4];
#pragma unroll
  for (int mt = 0; mt < 2; mt++)
#pragma unroll
    for (int nt = 0; nt < 8; nt++)
#pragma unroll
      for (int j = 0; j < 4; j++) acc[mt][nt][j] = 0.f;

#pragma unroll
  for (int i = 0; i < 8; i++) CP_ASYNC16(sb + ld_dst[i], ld_src[i]);
  CP_COMMIT();

#pragma unroll 1
  for (int kc = 0; kc < 128; kc++) {
    const int p = kc & 1;
    if (kc + 1 < 128) {
      const uint32_t qb = sb + (p ^ 1) * STAGE_B;
      const int ko = (kc + 1) * 32;
#pragma unroll
      for (int i = 0; i < 8; i++) CP_ASYNC16(qb + ld_dst[i], ld_src[i] + ko);
      CP_COMMIT();
      CP_WAIT(1);
    } else {
      CP_WAIT(0);
    }
    __syncthreads();

    const uint32_t base = sb + p * STAGE_B;
#pragma unroll
    for (int ks = 0; ks < 32; ks += 16) {
      uint32_t ah[2][4], al[2][4];
#pragma unroll
      for (int mt = 0; mt < 2; mt++) {
        uint32_t ro = (m0 + mt * 16 + a_lrow) * 80 + (ks + a_lk) * 2;
        ldsm_x4(ah[mt], base + ro);
        ldsm_x4(al[mt], base + 10240 + ro);
      }
      uint32_t bh[8][2], bl[8][2];
#pragma unroll
      for (int nt2 = 0; nt2 < 4; nt2++) {
        uint32_t ro = (n0 + nt2 * 16 + b_lrow) * 80 + (ks + b_lk) * 2;
        uint32_t t0[4], t1[4];
        ldsm_x4(t0, base + 20480 + ro);
        ldsm_x4(t1, base + 30720 + ro);
        bh[nt2 * 2][0] = t0[0]; bh[nt2 * 2][1] = t0[1];
        bh[nt2 * 2 + 1][0] = t0[2]; bh[nt2 * 2 + 1][1] = t0[3];
        bl[nt2 * 2][0] = t1[0]; bl[nt2 * 2][1] = t1[1];
        bl[nt2 * 2 + 1][0] = t1[2]; bl[nt2 * 2 + 1][1] = t1[3];
      }
#pragma unroll
      for (int mt = 0; mt < 2; mt++)
#pragma unroll
        for (int nt = 0; nt < 8; nt++) {
          mma_bf16(acc[mt][nt], ah[mt], bh[nt]);
          mma_bf16(acc[mt][nt], ah[mt], bl[nt]);
          mma_bf16(acc[mt][nt], al[mt], bh[nt]);
        }
    }
    __syncthreads();
  }

#pragma unroll
  for (int mt = 0; mt < 2; mt++)
#pragma unroll
    for (int nt = 0; nt < 8; nt++) {
      int m = row0 + m0 + mt * 16 + (lane >> 2);
      int n = col0 + n0 + nt * 8 + (lane & 3) * 2;
      *(float2*)&C[(size_t)m * Ntot + n] =
          make_float2(acc[mt][nt][0], acc[mt][nt][1]);
      *(float2*)&C[(size_t)(m + 8) * Ntot + n] =
          make_float2(acc[mt][nt][2], acc[mt][nt][3]);
    }
}

// ---------------------------------------------------------------------------
// RoPE: fp32 in -> bf16 out
// ---------------------------------------------------------------------------
__global__ void __launch_bounds__(256) rope_bf16_kernel(
    const float* __restrict__ x, const float* __restrict__ cs,
    const float* __restrict__ sn, __nv_bfloat16* __restrict__ out, int nheads) {
  int idx = blockIdx.x * 256 + threadIdx.x;
  int d = idx & 63;
  int h = (idx >> 6) % nheads;
  int t = idx / (64 * nheads);
  float c1 = cs[t * 128 + d],      s1 = sn[t * 128 + d];
  float c2 = cs[t * 128 + d + 64], s2 = sn[t * 128 + d + 64];
  const float* row = x + (size_t)t * (nheads * 128) + h * 128;
  __nv_bfloat16* orow = out + (size_t)t * (nheads * 128) + h * 128;
  float x1 = row[d], x2 = row[d + 64];
  orow[d]      = __float2bfloat16(x1 * c1 - x2 * s1);
  orow[d + 64] = __float2bfloat16(x2 * c2 + x1 * s2);
}

// V split: fp32 -> bf16 hi + lo
__global__ void __launch_bounds__(256) vsplit_kernel(
    const float* __restrict__ in, __nv_bfloat16* __restrict__ oh,
    __nv_bfloat16* __restrict__ ol) {
  size_t i = (size_t)blockIdx.x * 256 + threadIdx.x;
  float v = in[i];
  __nv_bfloat16 h = __float2bfloat16(v);
  oh[i] = h;
  ol[i] = __float2bfloat16(v - __bfloat162float(h));
}

// ---------------------------------------------------------------------------
// Flash attention with mma.sync bf16 (unchanged from passing round 7)
// ---------------------------------------------------------------------------
#define FP 136
#define FLASH_SMEM (4 * 64 * FP * 2)

__global__ void __launch_bounds__(128) flash_mma_kernel(
    const __nv_bfloat16* __restrict__ Qbf, const __nv_bfloat16* __restrict__ Kbf,
    const __nv_bfloat16* __restrict__ Vh, const __nv_bfloat16* __restrict__ Vl,
    float* __restrict__ O) {
  extern __shared__ __align__(1024) char smem[];
  __nv_bfloat16* Qs  = (__nv_bfloat16*)smem;
  __nv_bfloat16* Ks  = Qs + 64 * FP;
  __nv_bfloat16* Vhs = Qs + 2 * 64 * FP;
  __nv_bfloat16* Vls = Qs + 3 * 64 * FP;

  const int h = blockIdx.y, kvh = h >> 2;
  const int qt = blockIdx.x, qbase = qt * 64;
  const int tid = threadIdx.x, w = tid >> 5, lane = tid & 31;
  const float scale = 0.08838834764831845f;

#pragma unroll
  for (int i = 0; i < 8; i++) {
    int idx = i * 128 + tid;
    int r = idx >> 4, c = idx & 15;
    *(float4*)&Qs[r * FP + c * 8] =
        *(const float4*)&Qbf[(size_t)(qbase + r) * (NH * HD) + h * HD + c * 8];
  }
  __syncthreads();

  const uint32_t a_lrow = (lane & 7) + ((lane >> 3) & 1) * 8;
  const uint32_t a_lk   = ((lane >> 4) & 1) * 8;
  const uint32_t b_lrow = (lane & 7) + ((lane >> 4) & 1) * 8;
  const uint32_t b_lk   = ((lane >> 3) & 1) * 8;
  uint32_t qa[8][4];
  {
    uint32_t qsb = smem_u32(Qs);
#pragma unroll
    for (int ks = 0; ks < 8; ks++)
      ldsm_x4(qa[ks], qsb + ((w * 16 + a_lrow) * FP + ks * 16 + a_lk) * 2);
  }

  const int row0 = qbase + w * 16 + (lane >> 2);
  const int row1 = row0 + 8;

  float m_i[2] = {-1e30f, -1e30f}, l_i[2] = {0.f, 0.f};
  float o[16][4];
#pragma unroll
  for (int nt = 0; nt < 16; nt++)
#pragma unroll
    for (int j = 0; j < 4; j++) o[nt][j] = 0.f;

  const uint32_t ksb = smem_u32(Ks), vhb = smem_u32(Vhs), vlb = smem_u32(Vls);

#pragma unroll 1
  for (int kt = 0; kt <= qt; kt++) {
    const int kbase = kt * 64;
    __syncthreads();
#pragma unroll
    for (int i = 0; i < 8; i++) {
      int idx = i * 128 + tid;
      int r = idx >> 4, c = idx & 15;
      size_t g = (size_t)(kbase + r) * (NKV * HD) + kvh * HD + c * 8;
      *(float4*)&Ks[r * FP + c * 8]  = *(const float4*)&Kbf[g];
      *(float4*)&Vhs[r * FP + c * 8] = *(const float4*)&Vh[g];
      *(float4*)&Vls[r * FP + c * 8] = *(const float4*)&Vl[g];
    }
    __syncthreads();

    float s[8][4];
#pragma unroll
    for (int nt = 0; nt < 8; nt++)
#pragma unroll
      for (int j = 0; j < 4; j++) s[nt][j] = 0.f;
#pragma unroll
    for (int np = 0; np < 4; np++) {
#pragma unroll
      for (int ks = 0; ks < 8; ks++) {
        uint32_t kb[4];
        ldsm_x4(kb, ksb + ((np * 16 + b_lrow) * FP + ks * 16 + b_lk) * 2);
        mma_bf16(s[np * 2],     qa[ks], kb);
        mma_bf16(s[np * 2 + 1], qa[ks], kb + 2);
      }
    }

    float rm0 = -1e30f, rm1 = -1e30f;
    const bool diag = (kt == qt);
#pragma unroll
    for (int nt = 0; nt < 8; nt++) {
      int c0 = kbase + nt * 8 + (lane & 3) * 2;
#pragma unroll
      for (int j = 0; j < 4; j++) s[nt][j] *= scale;
      if (diag) {
        if (c0     > row0) s[nt][0] = -1e30f;
        if (c0 + 1 > row0) s[nt][1] = -1e30f;
        if (c0     > row1) s[nt][2] = -1e30f;
        if (c0 + 1 > row1) s[nt][3] = -1e30f;
      }
      rm0 = fmaxf(rm0, fmaxf(s[nt][0], s[nt][1]));
      rm1 = fmaxf(rm1, fmaxf(s[nt][2], s[nt][3]));
    }
#pragma unroll
    for (int off = 1; off <= 2; off <<= 1) {
      rm0 = fmaxf(rm0, __shfl_xor_sync(0xffffffffu, rm0, off));
      rm1 = fmaxf(rm1, __shfl_xor_sync(0xffffffffu, rm1, off));
    }
    float mn0 = fmaxf(m_i[0], rm0), mn1 = fmaxf(m_i[1], rm1);
    float cor0 = __expf(m_i[0] - mn0), cor1 = __expf(m_i[1] - mn1);
    float rs0 = 0.f, rs1 = 0.f;
#pragma unroll
    for (int nt = 0; nt < 8; nt++) {
      s[nt][0] = __expf(s[nt][0] - mn0); rs0 += s[nt][0];
      s[nt][1] = __expf(s[nt][1] - mn0); rs0 += s[nt][1];
      s[nt][2] = __expf(s[nt][2] - mn1); rs1 += s[nt][2];
      s[nt][3] = __expf(s[nt][3] - mn1); rs1 += s[nt][3];
    }
#pragma unroll
    for (int off = 1; off <= 2; off <<= 1) {
      rs0 += __shfl_xor_sync(0xffffffffu, rs0, off);
      rs1 += __shfl_xor_sync(0xffffffffu, rs1, off);
    }
    l_i[0] = l_i[0] * cor0 + rs0; m_i[0] = mn0;
    l_i[1] = l_i[1] * cor1 + rs1; m_i[1] = mn1;
#pragma unroll
    for (int nt = 0; nt < 16; nt++) {
      o[nt][0] *= cor0; o[nt][1] *= cor0;
      o[nt][2] *= cor1; o[nt][3] *= cor1;
    }

#pragma unroll
    for (int kk = 0; kk < 4; kk++) {
      float* p0 = s[kk * 2];
      float* p1 = s[kk * 2 + 1];
      uint32_t ph[4], pl[4];
      ph[0] = pkbf(p0[0], p0[1]); ph[1] = pkbf(p0[2], p0[3]);
      ph[2] = pkbf(p1[0], p1[1]); ph[3] = pkbf(p1[2], p1[3]);
      float q00 = p0[0] - __bfloat162float(__float2bfloat16(p0[0]));
      float q01 = p0[1] - __bfloat162float(__float2bfloat16(p0[1]));
      float q02 = p0[2] - __bfloat162float(__float2bfloat16(p0[2]));
      float q03 = p0[3] - __bfloat162float(__float2bfloat16(p0[3]));
      float q10 = p1[0] - __bfloat162float(__float2bfloat16(p1[0]));
      float q11 = p1[1] - __bfloat162float(__float2bfloat16(p1[1]));
      float q12 = p1[2] - __bfloat162float(__float2bfloat16(p1[2]));
      float q13 = p1[3] - __bfloat162float(__float2bfloat16(p1[3]));
      pl[0] = pkbf(q00, q01); pl[1] = pkbf(q02, q03);
      pl[2] = pkbf(q10, q11); pl[3] = pkbf(q12, q13);

      uint32_t vro = ((kk * 16 + (lane & 15)) * FP + ((lane >> 4) << 3)) * 2;
#pragma unroll
      for (int ntp = 0; ntp < 8; ntp++) {
        uint32_t vh4[4], vl4[4];
        ldsm_x4_t(vh4, vhb + vro + ntp * 32);
        ldsm_x4_t(vl4, vlb + vro + ntp * 32);
        mma_bf16(o[ntp * 2],     ph, vh4);
        mma_bf16(o[ntp * 2 + 1], ph, vh4 + 2);
        mma_bf16(o[ntp * 2],     ph, vl4);
        mma_bf16(o[ntp * 2 + 1], ph, vl4 + 2);
        mma_bf16(o[ntp * 2],     pl, vh4);
        mma_bf16(o[ntp * 2 + 1], pl, vh4 + 2);
      }
    }
  }

  float rl0 = 1.0f / l_i[0], rl1 = 1.0f / l_i[1];
#pragma unroll
  for (int nt = 0; nt < 16; nt++) {
    int col = h * HD + nt * 8 + (lane & 3) * 2;
    *(float2*)&O[(size_t)row0 * (NH * HD) + col] =
        make_float2(o[nt][0] * rl0, o[nt][1] * rl0);
    *(float2*)&O[(size_t)row1 * (NH * HD) + col] =
        make_float2(o[nt][2] * rl1, o[nt][3] * rl1);
  }
}

// ---------------------------------------------------------------------------
// Host launcher
// ---------------------------------------------------------------------------
extern "C" void kernel_launch(void* const* d_in, const int* in_sizes, int n_in,
                              void* d_out, int out_size) {
  const float* hidden = (const float*)d_in[0];
  const float* Wq = (const float*)d_in[1];
  const float* Wk = (const float*)d_in[2];
  const float* Wv = (const float*)d_in[3];
  const float* Wo = (const float*)d_in[4];
  const float* cosp = (const float*)d_in[5];
  const float* sinp = (const float*)d_in[6];
  const int* qcol = (const int*)d_in[8];
  const int* qrow = (const int*)d_in[9];
  const int* kcol = (const int*)d_in[10];
  const int* krow = (const int*)d_in[11];
  const int* vcol = (const int*)d_in[12];
  const int* vrow = (const int*)d_in[13];
  const int* ocol = (const int*)d_in[14];
  const int* orow = (const int*)d_in[15];

  __nv_bfloat16 *hqh, *hql, *hkh, *hkl, *hvh, *hvl, *aoh, *aol;
  __nv_bfloat16 *wqh, *wql, *wkh, *wkl, *wvh, *wvl, *woh, *wol;
  __nv_bfloat16 *Qbf, *Kbf, *Vhb, *Vlb;
  float *Qb, *Kb, *Vb, *Ab;
  cudaGetSymbolAddress((void**)&hqh, g_hq_h); cudaGetSymbolAddress((void**)&hql, g_hq_l);
  cudaGetSymbolAddress((void**)&hkh, g_hk_h); cudaGetSymbolAddress((void**)&hkl, g_hk_l);
  cudaGetSymbolAddress((void**)&hvh, g_hv_h); cudaGetSymbolAddress((void**)&hvl, g_hv_l);
  cudaGetSymbolAddress((void**)&aoh, g_ao_h); cudaGetSymbolAddress((void**)&aol, g_ao_l);
  cudaGetSymbolAddress((void**)&wqh, g_wq_h); cudaGetSymbolAddress((void**)&wql, g_wq_l);
  cudaGetSymbolAddress((void**)&wkh, g_wk_h); cudaGetSymbolAddress((void**)&wkl, g_wk_l);
  cudaGetSymbolAddress((void**)&wvh, g_wv_h); cudaGetSymbolAddress((void**)&wvl, g_wv_l);
  cudaGetSymbolAddress((void**)&woh, g_wo_h); cudaGetSymbolAddress((void**)&wol, g_wo_l);
  cudaGetSymbolAddress((void**)&Qb, g_Q);
  cudaGetSymbolAddress((void**)&Kb, g_K);
  cudaGetSymbolAddress((void**)&Vb, g_V);
  cudaGetSymbolAddress((void**)&Ab, g_A);
  cudaGetSymbolAddress((void**)&Qbf, g_Qbf);
  cudaGetSymbolAddress((void**)&Kbf, g_Kbf);
  cudaGetSymbolAddress((void**)&Vhb, g_Vhb);
  cudaGetSymbolAddress((void**)&Vlb, g_Vlb);

  cudaFuncSetAttribute(gemm_mma_kernel,
                       cudaFuncAttributeMaxDynamicSharedMemorySize, GEMM_SMEM);
  cudaFuncSetAttribute(flash_mma_kernel,
                       cudaFuncAttributeMaxDynamicSharedMemorySize, FLASH_SMEM);

  // Fused QKV gather + hi/lo convert (one pass over hidden)
  gather3_convert_kernel<<<SEQ, 256>>>(hidden, qcol, kcol, vcol,
                                       hqh, hql, hkh, hkl, hvh, hvl);

  // Weight converts (row-perm folded), vectorized
  wconvert_kernel<<<dim3(4, 4096), 256>>>(Wq, qrow, wqh, wql);
  wconvert_kernel<<<dim3(4, 1024), 256>>>(Wk, krow, wkh, wkl);
  wconvert_kernel<<<dim3(4, 1024), 256>>>(Wv, vrow, wvh, wvl);
  wconvert_kernel<<<dim3(4, 4096), 256>>>(Wo, orow, woh, wol);

  // Q projection (z=1 unused -> same pointers)
  gemm_mma_kernel<<<dim3(16, 32, 1), 256, GEMM_SMEM>>>(
      hqh, hql, wqh, wql, Qb, 4096, hqh, hql, wqh, wql, Qb);
  // K and V projections fused into one launch via gridDim.z
  gemm_mma_kernel<<<dim3(16, 8, 2), 256, GEMM_SMEM>>>(
      hkh, hkl, wkh, wkl, Kb, 1024, hvh, hvl, wvh, wvl, Vb);

  rope_bf16_kernel<<<(SEQ * NH * 64) / 256, 256>>>(Qb, cosp, sinp, Qbf, NH);
  rope_bf16_kernel<<<(SEQ * NKV * 64) / 256, 256>>>(Kb, cosp, sinp, Kbf, NKV);
  vsplit_kernel<<<(SEQ * NKV * HD) / 256, 256>>>(Vb, Vhb, Vlb);

  flash_mma_kernel<<<dim3(SEQ / 64, NH), 128, FLASH_SMEM>>>(Qbf, Kbf, Vhb, Vlb, Ab);

  gather1_convert_kernel<<<SEQ, 256>>>(Ab, ocol, aoh, aol);
  gemm_mma_kernel<<<dim3(16, 32, 1), 256, GEMM_SMEM>>>(
      aoh, aol, woh, wol, (float*)d_out, 4096, aoh, aol, woh, wol, (float*)d_out);
}

// round 10
// speedup vs baseline: 5.1060x; 1.4282x over previous
#include <cuda_runtime.h>
#include <cuda_bf16.h>
#include <cuda_fp16.h>
#include <cstdint>

#define SEQ   2048
#define HDIM  4096
#define NH    32
#define NKV   8
#define HD    128

// ---------------------------------------------------------------------------
// Scratch (__device__ globals; no cudaMalloc allowed)
// ---------------------------------------------------------------------------
__device__ __half g_hq16[SEQ * HDIM], g_hk16[SEQ * HDIM], g_hv16[SEQ * HDIM];
__device__ __half g_wq16[4096 * 4096], g_wk16[1024 * 4096], g_wv16[1024 * 4096];
__device__ __nv_bfloat16 g_ao_h[SEQ * HDIM], g_ao_l[SEQ * HDIM];
__device__ __nv_bfloat16 g_wo_h[4096 * 4096], g_wo_l[4096 * 4096];
__device__ float g_Q[SEQ * NH * HD];
__device__ float g_K[SEQ * NKV * HD];
__device__ float g_V[SEQ * NKV * HD];
__device__ float g_A[SEQ * NH * HD];
__device__ __nv_bfloat16 g_Qbf[SEQ * NH * HD];
__device__ __nv_bfloat16 g_Kbf[SEQ * NKV * HD];
__device__ __nv_bfloat16 g_Vhb[SEQ * NKV * HD];
__device__ __nv_bfloat16 g_Vlb[SEQ * NKV * HD];

// ---------------------------------------------------------------------------
// PTX helpers (baseline PTX only; works on plain sm_103 target)
// ---------------------------------------------------------------------------
static __device__ __forceinline__ uint32_t smem_u32(const void* p) {
  uint32_t a;
  asm("{ .reg .u64 t; cvta.to.shared.u64 t, %1; cvt.u32.u64 %0, t; }"
      : "=r"(a) : "l"(p));
  return a;
}

#define CP_ASYNC16(dst, src) \
  asm volatile("cp.async.cg.shared.global [%0], [%1], 16;" :: "r"(dst), "l"(src))
#define CP_COMMIT()   asm volatile("cp.async.commit_group;" ::: "memory")
#define CP_WAIT(n)    asm volatile("cp.async.wait_group %0;" :: "n"(n) : "memory")

static __device__ __forceinline__ void ldsm_x4(uint32_t* r, uint32_t addr) {
  asm volatile("ldmatrix.sync.aligned.m8n8.x4.shared.b16 {%0,%1,%2,%3}, [%4];"
               : "=r"(r[0]), "=r"(r[1]), "=r"(r[2]), "=r"(r[3]) : "r"(addr));
}
static __device__ __forceinline__ void ldsm_x4_t(uint32_t* r, uint32_t addr) {
  asm volatile("ldmatrix.sync.aligned.m8n8.x4.trans.shared.b16 {%0,%1,%2,%3}, [%4];"
               : "=r"(r[0]), "=r"(r[1]), "=r"(r[2]), "=r"(r[3]) : "r"(addr));
}

static __device__ __forceinline__ void mma_bf16(float* d, const uint32_t* a,
                                                const uint32_t* b) {
  asm volatile(
      "mma.sync.aligned.m16n8k16.row.col.f32.bf16.bf16.f32 "
      "{%0,%1,%2,%3}, {%4,%5,%6,%7}, {%8,%9}, {%0,%1,%2,%3};"
      : "+f"(d[0]), "+f"(d[1]), "+f"(d[2]), "+f"(d[3])
      : "r"(a[0]), "r"(a[1]), "r"(a[2]), "r"(a[3]), "r"(b[0]), "r"(b[1]));
}
static __device__ __forceinline__ void mma_f16(float* d, const uint32_t* a,
                                               const uint32_t* b) {
  asm volatile(
      "mma.sync.aligned.m16n8k16.row.col.f32.f16.f16.f32 "
      "{%0,%1,%2,%3}, {%4,%5,%6,%7}, {%8,%9}, {%0,%1,%2,%3};"
      : "+f"(d[0]), "+f"(d[1]), "+f"(d[2]), "+f"(d[3])
      : "r"(a[0]), "r"(a[1]), "r"(a[2]), "r"(a[3]), "r"(b[0]), "r"(b[1]));
}

static __device__ __forceinline__ uint32_t pkbf(float a, float b) {
  __nv_bfloat162 t = __floats2bfloat162_rn(a, b);
  return *(uint32_t*)&t;
}
static __device__ __forceinline__ uint32_t pkhf(float a, float b) {
  __half2 t = __floats2half2_rn(a, b);
  return *(uint32_t*)&t;
}

// ---------------------------------------------------------------------------
// Fused 3-way gather + fp16 convert (QKV path): per-row smem staging.
// ---------------------------------------------------------------------------
__global__ void __launch_bounds__(256) gather3_convert_kernel(
    const float* __restrict__ in,
    const int* __restrict__ qi, const int* __restrict__ ki,
    const int* __restrict__ vi,
    __half* __restrict__ q16, __half* __restrict__ k16,
    __half* __restrict__ v16) {
  __shared__ __align__(16) float row[HDIM];
  const int t = blockIdx.x;
  const float* src = in + (size_t)t * HDIM;
#pragma unroll
  for (int i = 0; i < 4; i++) {
    int e = (i * 256 + threadIdx.x) * 4;
    *(float4*)&row[e] = *(const float4*)&src[e];
  }
  __syncthreads();
  const size_t base = (size_t)t * HDIM;
#pragma unroll
  for (int i = 0; i < 16; i++) {
    int c = i * 256 + threadIdx.x;
    q16[base + c] = __float2half_rn(row[qi[c]]);
    k16[base + c] = __float2half_rn(row[ki[c]]);
    v16[base + c] = __float2half_rn(row[vi[c]]);
  }
}

// Single-perm bf16 hi/lo variant (O path)
__global__ void __launch_bounds__(256) gather1_convert_kernel(
    const float* __restrict__ in, const int* __restrict__ idx,
    __nv_bfloat16* __restrict__ oh, __nv_bfloat16* __restrict__ ol) {
  __shared__ __align__(16) float row[HDIM];
  const int t = blockIdx.x;
  const float* src = in + (size_t)t * HDIM;
#pragma unroll
  for (int i = 0; i < 4; i++) {
    int e = (i * 256 + threadIdx.x) * 4;
    *(float4*)&row[e] = *(const float4*)&src[e];
  }
  __syncthreads();
  const size_t base = (size_t)t * HDIM;
#pragma unroll
  for (int i = 0; i < 16; i++) {
    int c = i * 256 + threadIdx.x;
    float v = row[idx[c]];
    __nv_bfloat16 h = __float2bfloat16(v);
    oh[base + c] = h;
    ol[base + c] = __float2bfloat16(v - __bfloat162float(h));
  }
}

// ---------------------------------------------------------------------------
// Weight converts (row-perm folded). fp16 single / bf16 hi-lo variants.
// grid = (HDIM/1024, nrows)
// ---------------------------------------------------------------------------
__global__ void __launch_bounds__(256) wconvert16_kernel(
    const float* __restrict__ W, const int* __restrict__ ridx,
    __half* __restrict__ o) {
  int j = blockIdx.y;
  int c4 = (blockIdx.x * 256 + threadIdx.x) * 4;
  float4 v = *(const float4*)&W[(size_t)ridx[j] * HDIM + c4];
  uint2 s;
  s.x = pkhf(v.x, v.y); s.y = pkhf(v.z, v.w);
  *(uint2*)&o[(size_t)j * HDIM + c4] = s;
}

__global__ void __launch_bounds__(256) wconvert_kernel(
    const float* __restrict__ W, const int* __restrict__ ridx,
    __nv_bfloat16* __restrict__ oh, __nv_bfloat16* __restrict__ ol) {
  int j = blockIdx.y;
  int c4 = (blockIdx.x * 256 + threadIdx.x) * 4;
  float4 v = *(const float4*)&W[(size_t)ridx[j] * HDIM + c4];
  __nv_bfloat16 h0 = __float2bfloat16(v.x), h1 = __float2bfloat16(v.y);
  __nv_bfloat16 h2 = __float2bfloat16(v.z), h3 = __float2bfloat16(v.w);
  uint2 hs, ls;
  hs.x = pkbf(v.x, v.y); hs.y = pkbf(v.z, v.w);
  ls.x = pkbf(v.x - __bfloat162float(h0), v.y - __bfloat162float(h1));
  ls.y = pkbf(v.z - __bfloat162float(h2), v.w - __bfloat162float(h3));
  *(uint2*)&oh[(size_t)j * HDIM + c4] = hs;
  *(uint2*)&ol[(size_t)j * HDIM + c4] = ls;
}

// ---------------------------------------------------------------------------
// Single-pass fp16 GEMM (QKV projections): C = A @ B^T, fp32 accum.
// BM=BN=128, BK=32, 8 warps x (32x64). Stage: A(10240B)+B(10240B), x2 buf.
// blockIdx.z selects between two problem sets (K/V fusion).
// ---------------------------------------------------------------------------
#define STAGE16_B 20480
#define GEMM16_SMEM (2 * STAGE16_B)

__global__ void __launch_bounds__(256) gemm16_mma_kernel(
    const __half* A_, const __half* B_, float* C_, int Ntot,
    const __half* A2, const __half* B2, float* C2) {
  const __half* A = A_; const __half* B = B_; float* C = C_;
  if (blockIdx.z == 1) { A = A2; B = B2; C = C2; }

  extern __shared__ __align__(1024) char smem[];
  uint32_t sb = smem_u32(smem);
  const int tid = threadIdx.x, wid = tid >> 5, lane = tid & 31;
  const int row0 = blockIdx.x * 128, col0 = blockIdx.y * 128;

  const __half* ld_src[4];
  uint32_t ld_dst[4];
#pragma unroll
  for (int i = 0; i < 4; i++) {
    int t = i * 256 + tid;
    int mat = t >> 9, r = (t >> 2) & 127, c = t & 3;
    const __half* base = (mat == 0) ? A + (size_t)row0 * 4096
                                    : B + (size_t)col0 * 4096;
    ld_src[i] = base + (size_t)r * 4096 + c * 8;
    ld_dst[i] = (uint32_t)(mat * 10240 + r * 80 + c * 16);
  }

  const int m0 = (wid & 3) * 32, n0 = (wid >> 2) * 64;
  const uint32_t a_lrow = (lane & 7) + ((lane >> 3) & 1) * 8;
  const uint32_t a_lk   = ((lane >> 4) & 1) * 8;
  const uint32_t b_lrow = (lane & 7) + ((lane >> 4) & 1) * 8;
  const uint32_t b_lk   = ((lane >> 3) & 1) * 8;

  float acc[2][8][4];
#pragma unroll
  for (int mt = 0; mt < 2; mt++)
#pragma unroll
    for (int nt = 0; nt < 8; nt++)
#pragma unroll
      for (int j = 0; j < 4; j++) acc[mt][nt][j] = 0.f;

#pragma unroll
  for (int i = 0; i < 4; i++) CP_ASYNC16(sb + ld_dst[i], ld_src[i]);
  CP_COMMIT();

#pragma unroll 1
  for (int kc = 0; kc < 128; kc++) {
    const int p = kc & 1;
    if (kc + 1 < 128) {
      const uint32_t qb = sb + (p ^ 1) * STAGE16_B;
      const int ko = (kc + 1) * 32;
#pragma unroll
      for (int i = 0; i < 4; i++) CP_ASYNC16(qb + ld_dst[i], ld_src[i] + ko);
      CP_COMMIT();
      CP_WAIT(1);
    } else {
      CP_WAIT(0);
    }
    __syncthreads();

    const uint32_t base = sb + p * STAGE16_B;
#pragma unroll
    for (int ks = 0; ks < 32; ks += 16) {
      uint32_t a4[2][4];
#pragma unroll
      for (int mt = 0; mt < 2; mt++)
        ldsm_x4(a4[mt], base + (m0 + mt * 16 + a_lrow) * 80 + (ks + a_lk) * 2);
      uint32_t b4[8][2];
#pragma unroll
      for (int nt2 = 0; nt2 < 4; nt2++) {
        uint32_t t0[4];
        ldsm_x4(t0, base + 10240 + (n0 + nt2 * 16 + b_lrow) * 80 + (ks + b_lk) * 2);
        b4[nt2 * 2][0] = t0[0]; b4[nt2 * 2][1] = t0[1];
        b4[nt2 * 2 + 1][0] = t0[2]; b4[nt2 * 2 + 1][1] = t0[3];
      }
#pragma unroll
      for (int mt = 0; mt < 2; mt++)
#pragma unroll
        for (int nt = 0; nt < 8; nt++)
          mma_f16(acc[mt][nt], a4[mt], b4[nt]);
    }
    __syncthreads();
  }

#pragma unroll
  for (int mt = 0; mt < 2; mt++)
#pragma unroll
    for (int nt = 0; nt < 8; nt++) {
      int m = row0 + m0 + mt * 16 + (lane >> 2);
      int n = col0 + n0 + nt * 8 + (lane & 3) * 2;
      *(float2*)&C[(size_t)m * Ntot + n] =
          make_float2(acc[mt][nt][0], acc[mt][nt][1]);
      *(float2*)&C[(size_t)(m + 8) * Ntot + n] =
          make_float2(acc[mt][nt][2], acc[mt][nt][3]);
    }
}

// ---------------------------------------------------------------------------
// 3-pass split-bf16 GEMM (O projection only; unchanged mainloop)
// ---------------------------------------------------------------------------
#define STAGE_B 40960
#define GEMM_SMEM (2 * STAGE_B)

__global__ void __launch_bounds__(256, 1) gemm_mma_kernel(
    const __nv_bfloat16* __restrict__ Ah, const __nv_bfloat16* __restrict__ Al,
    const __nv_bfloat16* __restrict__ Bh, const __nv_bfloat16* __restrict__ Bl,
    float* __restrict__ C, int Ntot) {
  extern __shared__ __align__(1024) char smem[];
  uint32_t sb = smem_u32(smem);
  const int tid = threadIdx.x, wid = tid >> 5, lane = tid & 31;
  const int row0 = blockIdx.x * 128, col0 = blockIdx.y * 128;

  const __nv_bfloat16* ld_src[8];
  uint32_t ld_dst[8];
#pragma unroll
  for (int i = 0; i < 8; i++) {
    int t = i * 256 + tid;
    int mat = t >> 9, r = (t >> 2) & 127, c = t & 3;
    const __nv_bfloat16* base =
        (mat == 0) ? Ah + (size_t)row0 * 4096 :
        (mat == 1) ? Al + (size_t)row0 * 4096 :
        (mat == 2) ? Bh + (size_t)col0 * 4096 :
                     Bl + (size_t)col0 * 4096;
    ld_src[i] = base + (size_t)r * 4096 + c * 8;
    ld_dst[i] = (uint32_t)(mat * 10240 + r * 80 + c * 16);
  }

  const int m0 = (wid & 3) * 32, n0 = (wid >> 2) * 64;
  const uint32_t a_lrow = (lane & 7) + ((lane >> 3) & 1) * 8;
  const uint32_t a_lk   = ((lane >> 4) & 1) * 8;
  const uint32_t b_lrow = (lane & 7) + ((lane >> 4) & 1) * 8;
  const uint32_t b_lk   = ((lane >> 3) & 1) * 8;

  float acc[2][8][4];
#pragma unroll
  for (int mt = 0; mt < 2; mt++)
#pragma unroll
    for (int nt = 0; nt < 8; nt++)
#pragma unroll
      for (int j = 0; j < 4; j++) acc[mt][nt][j] = 0.f;

#pragma unroll
  for (int i = 0; i < 8; i++) CP_ASYNC16(sb + ld_dst[i], ld_src[i]);
  CP_COMMIT();

#pragma unroll 1
  for (int kc = 0; kc < 128; kc++) {
    const int p = kc & 1;
    if (kc + 1 < 128) {
      const uint32_t qb = sb + (p ^ 1) * STAGE_B;
      const int ko = (kc + 1) * 32;
#pragma unroll
      for (int i = 0; i < 8; i++) CP_ASYNC16(qb + ld_dst[i], ld_src[i] + ko);
      CP_COMMIT();
      CP_WAIT(1);
    } else {
      CP_WAIT(0);
    }
    __syncthreads();

    const uint32_t base = sb + p * STAGE_B;
#pragma unroll
    for (int ks = 0; ks < 32; ks += 16) {
      uint32_t ah[2][4], al[2][4];
#pragma unroll
      for (int mt = 0; mt < 2; mt++) {
        uint32_t ro = (m0 + mt * 16 + a_lrow) * 80 + (ks + a_lk) * 2;
        ldsm_x4(ah[mt], base + ro);
        ldsm_x4(al[mt], base + 10240 + ro);
      }
      uint32_t bh[8][2], bl[8][2];
#pragma unroll
      for (int nt2 = 0; nt2 < 4; nt2++) {
        uint32_t ro = (n0 + nt2 * 16 + b_lrow) * 80 + (ks + b_lk) * 2;
        uint32_t t0[4], t1[4];
        ldsm_x4(t0, base + 20480 + ro);
        ldsm_x4(t1, base + 30720 + ro);
        bh[nt2 * 2][0] = t0[0]; bh[nt2 * 2][1] = t0[1];
        bh[nt2 * 2 + 1][0] = t0[2]; bh[nt2 * 2 + 1][1] = t0[3];
        bl[nt2 * 2][0] = t1[0]; bl[nt2 * 2][1] = t1[1];
        bl[nt2 * 2 + 1][0] = t1[2]; bl[nt2 * 2 + 1][1] = t1[3];
      }
#pragma unroll
      for (int mt = 0; mt < 2; mt++)
#pragma unroll
        for (int nt = 0; nt < 8; nt++) {
          mma_bf16(acc[mt][nt], ah[mt], bh[nt]);
          mma_bf16(acc[mt][nt], ah[mt], bl[nt]);
          mma_bf16(acc[mt][nt], al[mt], bh[nt]);
        }
    }
    __syncthreads();
  }

#pragma unroll
  for (int mt = 0; mt < 2; mt++)
#pragma unroll
    for (int nt = 0; nt < 8; nt++) {
      int m = row0 + m0 + mt * 16 + (lane >> 2);
      int n = col0 + n0 + nt * 8 + (lane & 3) * 2;
      *(float2*)&C[(size_t)m * Ntot + n] =
          make_float2(acc[mt][nt][0], acc[mt][nt][1]);
      *(float2*)&C[(size_t)(m + 8) * Ntot + n] =
          make_float2(acc[mt][nt][2], acc[mt][nt][3]);
    }
}

// ---------------------------------------------------------------------------
// RoPE: fp32 in -> bf16 out
// ---------------------------------------------------------------------------
__global__ void __launch_bounds__(256) rope_bf16_kernel(
    const float* __restrict__ x, const float* __restrict__ cs,
    const float* __restrict__ sn, __nv_bfloat16* __restrict__ out, int nheads) {
  int idx = blockIdx.x * 256 + threadIdx.x;
  int d = idx & 63;
  int h = (idx >> 6) % nheads;
  int t = idx / (64 * nheads);
  float c1 = cs[t * 128 + d],      s1 = sn[t * 128 + d];
  float c2 = cs[t * 128 + d + 64], s2 = sn[t * 128 + d + 64];
  const float* row = x + (size_t)t * (nheads * 128) + h * 128;
  __nv_bfloat16* orow = out + (size_t)t * (nheads * 128) + h * 128;
  float x1 = row[d], x2 = row[d + 64];
  orow[d]      = __float2bfloat16(x1 * c1 - x2 * s1);
  orow[d + 64] = __float2bfloat16(x2 * c2 + x1 * s2);
}

// V split: fp32 -> bf16 hi + lo
__global__ void __launch_bounds__(256) vsplit_kernel(
    const float* __restrict__ in, __nv_bfloat16* __restrict__ oh,
    __nv_bfloat16* __restrict__ ol) {
  size_t i = (size_t)blockIdx.x * 256 + threadIdx.x;
  float v = in[i];
  __nv_bfloat16 h = __float2bfloat16(v);
  oh[i] = h;
  ol[i] = __float2bfloat16(v - __bfloat162float(h));
}

// ---------------------------------------------------------------------------
// Flash attention with mma.sync bf16 (unchanged from passing round)
// ---------------------------------------------------------------------------
#define FP 136
#define FLASH_SMEM (4 * 64 * FP * 2)

__global__ void __launch_bounds__(128) flash_mma_kernel(
    const __nv_bfloat16* __restrict__ Qbf, const __nv_bfloat16* __restrict__ Kbf,
    const __nv_bfloat16* __restrict__ Vh, const __nv_bfloat16* __restrict__ Vl,
    float* __restrict__ O) {
  extern __shared__ __align__(1024) char smem[];
  __nv_bfloat16* Qs  = (__nv_bfloat16*)smem;
  __nv_bfloat16* Ks  = Qs + 64 * FP;
  __nv_bfloat16* Vhs = Qs + 2 * 64 * FP;
  __nv_bfloat16* Vls = Qs + 3 * 64 * FP;

  const int h = blockIdx.y, kvh = h >> 2;
  const int qt = blockIdx.x, qbase = qt * 64;
  const int tid = threadIdx.x, w = tid >> 5, lane = tid & 31;
  const float scale = 0.08838834764831845f;

#pragma unroll
  for (int i = 0; i < 8; i++) {
    int idx = i * 128 + tid;
    int r = idx >> 4, c = idx & 15;
    *(float4*)&Qs[r * FP + c * 8] =
        *(const float4*)&Qbf[(size_t)(qbase + r) * (NH * HD) + h * HD + c * 8];
  }
  __syncthreads();

  const uint32_t a_lrow = (lane & 7) + ((lane >> 3) & 1) * 8;
  const uint32_t a_lk   = ((lane >> 4) & 1) * 8;
  const uint32_t b_lrow = (lane & 7) + ((lane >> 4) & 1) * 8;
  const uint32_t b_lk   = ((lane >> 3) & 1) * 8;
  uint32_t qa[8][4];
  {
    uint32_t qsb = smem_u32(Qs);
#pragma unroll
    for (int ks = 0; ks < 8; ks++)
      ldsm_x4(qa[ks], qsb + ((w * 16 + a_lrow) * FP + ks * 16 + a_lk) * 2);
  }

  const int row0 = qbase + w * 16 + (lane >> 2);
  const int row1 = row0 + 8;

  float m_i[2] = {-1e30f, -1e30f}, l_i[2] = {0.f, 0.f};
  float o[16][4];
#pragma unroll
  for (int nt = 0; nt < 16; nt++)
#pragma unroll
    for (int j = 0; j < 4; j++) o[nt][j] = 0.f;

  const uint32_t ksb = smem_u32(Ks), vhb = smem_u32(Vhs), vlb = smem_u32(Vls);

#pragma unroll 1
  for (int kt = 0; kt <= qt; kt++) {
    const int kbase = kt * 64;
    __syncthreads();
#pragma unroll
    for (int i = 0; i < 8; i++) {
      int idx = i * 128 + tid;
      int r = idx >> 4, c = idx & 15;
      size_t g = (size_t)(kbase + r) * (NKV * HD) + kvh * HD + c * 8;
      *(float4*)&Ks[r * FP + c * 8]  = *(const float4*)&Kbf[g];
      *(float4*)&Vhs[r * FP + c * 8] = *(const float4*)&Vh[g];
      *(float4*)&Vls[r * FP + c * 8] = *(const float4*)&Vl[g];
    }
    __syncthreads();

    float s[8][4];
#pragma unroll
    for (int nt = 0; nt < 8; nt++)
#pragma unroll
      for (int j = 0; j < 4; j++) s[nt][j] = 0.f;
#pragma unroll
    for (int np = 0; np < 4; np++) {
#pragma unroll
      for (int ks = 0; ks < 8; ks++) {
        uint32_t kb[4];
        ldsm_x4(kb, ksb + ((np * 16 + b_lrow) * FP + ks * 16 + b_lk) * 2);
        mma_bf16(s[np * 2],     qa[ks], kb);
        mma_bf16(s[np * 2 + 1], qa[ks], kb + 2);
      }
    }

    float rm0 = -1e30f, rm1 = -1e30f;
    const bool diag = (kt == qt);
#pragma unroll
    for (int nt = 0; nt < 8; nt++) {
      int c0 = kbase + nt * 8 + (lane & 3) * 2;
#pragma unroll
      for (int j = 0; j < 4; j++) s[nt][j] *= scale;
      if (diag) {
        if (c0     > row0) s[nt][0] = -1e30f;
        if (c0 + 1 > row0) s[nt][1] = -1e30f;
        if (c0     > row1) s[nt][2] = -1e30f;
        if (c0 + 1 > row1) s[nt][3] = -1e30f;
      }
      rm0 = fmaxf(rm0, fmaxf(s[nt][0], s[nt][1]));
      rm1 = fmaxf(rm1, fmaxf(s[nt][2], s[nt][3]));
    }
#pragma unroll
    for (int off = 1; off <= 2; off <<= 1) {
      rm0 = fmaxf(rm0, __shfl_xor_sync(0xffffffffu, rm0, off));
      rm1 = fmaxf(rm1, __shfl_xor_sync(0xffffffffu, rm1, off));
    }
    float mn0 = fmaxf(m_i[0], rm0), mn1 = fmaxf(m_i[1], rm1);
    float cor0 = __expf(m_i[0] - mn0), cor1 = __expf(m_i[1] - mn1);
    float rs0 = 0.f, rs1 = 0.f;
#pragma unroll
    for (int nt = 0; nt < 8; nt++) {
      s[nt][0] = __expf(s[nt][0] - mn0); rs0 += s[nt][0];
      s[nt][1] = __expf(s[nt][1] - mn0); rs0 += s[nt][1];
      s[nt][2] = __expf(s[nt][2] - mn1); rs1 += s[nt][2];
      s[nt][3] = __expf(s[nt][3] - mn1); rs1 += s[nt][3];
    }
#pragma unroll
    for (int off = 1; off <= 2; off <<= 1) {
      rs0 += __shfl_xor_sync(0xffffffffu, rs0, off);
      rs1 += __shfl_xor_sync(0xffffffffu, rs1, off);
    }
    l_i[0] = l_i[0] * cor0 + rs0; m_i[0] = mn0;
    l_i[1] = l_i[1] * cor1 + rs1; m_i[1] = mn1;
#pragma unroll
    for (int nt = 0; nt < 16; nt++) {
      o[nt][0] *= cor0; o[nt][1] *= cor0;
      o[nt][2] *= cor1; o[nt][3] *= cor1;
    }

#pragma unroll
    for (int kk = 0; kk < 4; kk++) {
      float* p0 = s[kk * 2];
      float* p1 = s[kk * 2 + 1];
      uint32_t ph[4], pl[4];
      ph[0] = pkbf(p0[0], p0[1]); ph[1] = pkbf(p0[2], p0[3]);
      ph[2] = pkbf(p1[0], p1[1]); ph[3] = pkbf(p1[2], p1[3]);
      float q00 = p0[0] - __bfloat162float(__float2bfloat16(p0[0]));
      float q01 = p0[1] - __bfloat162float(__float2bfloat16(p0[1]));
      float q02 = p0[2] - __bfloat162float(__float2bfloat16(p0[2]));
      float q03 = p0[3] - __bfloat162float(__float2bfloat16(p0[3]));
      float q10 = p1[0] - __bfloat162float(__float2bfloat16(p1[0]));
      float q11 = p1[1] - __bfloat162float(__float2bfloat16(p1[1]));
      float q12 = p1[2] - __bfloat162float(__float2bfloat16(p1[2]));
      float q13 = p1[3] - __bfloat162float(__float2bfloat16(p1[3]));
      pl[0] = pkbf(q00, q01); pl[1] = pkbf(q02, q03);
      pl[2] = pkbf(q10, q11); pl[3] = pkbf(q12, q13);

      uint32_t vro = ((kk * 16 + (lane & 15)) * FP + ((lane >> 4) << 3)) * 2;
#pragma unroll
      for (int ntp = 0; ntp < 8; ntp++) {
        uint32_t vh4[4], vl4[4];
        ldsm_x4_t(vh4, vhb + vro + ntp * 32);
        ldsm_x4_t(vl4, vlb + vro + ntp * 32);
        mma_bf16(o[ntp * 2],     ph, vh4);
        mma_bf16(o[ntp * 2 + 1], ph, vh4 + 2);
        mma_bf16(o[ntp * 2],     ph, vl4);
        mma_bf16(o[ntp * 2 + 1], ph, vl4 + 2);
        mma_bf16(o[ntp * 2],     pl, vh4);
        mma_bf16(o[ntp * 2 + 1], pl, vh4 + 2);
      }
    }
  }

  float rl0 = 1.0f / l_i[0], rl1 = 1.0f / l_i[1];
#pragma unroll
  for (int nt = 0; nt < 16; nt++) {
    int col = h * HD + nt * 8 + (lane & 3) * 2;
    *(float2*)&O[(size_t)row0 * (NH * HD) + col] =
        make_float2(o[nt][0] * rl0, o[nt][1] * rl0);
    *(float2*)&O[(size_t)row1 * (NH * HD) + col] =
        make_float2(o[nt][2] * rl1, o[nt][3] * rl1);
  }
}

// ---------------------------------------------------------------------------
// Host launcher
// ---------------------------------------------------------------------------
extern "C" void kernel_launch(void* const* d_in, const int* in_sizes, int n_in,
                              void* d_out, int out_size) {
  const float* hidden = (const float*)d_in[0];
  const float* Wq = (const float*)d_in[1];
  const float* Wk = (const float*)d_in[2];
  const float* Wv = (const float*)d_in[3];
  const float* Wo = (const float*)d_in[4];
  const float* cosp = (const float*)d_in[5];
  const float* sinp = (const float*)d_in[6];
  const int* qcol = (const int*)d_in[8];
  const int* qrow = (const int*)d_in[9];
  const int* kcol = (const int*)d_in[10];
  const int* krow = (const int*)d_in[11];
  const int* vcol = (const int*)d_in[12];
  const int* vrow = (const int*)d_in[13];
  const int* ocol = (const int*)d_in[14];
  const int* orow = (const int*)d_in[15];

  __half *hq16, *hk16, *hv16, *wq16, *wk16, *wv16;
  __nv_bfloat16 *aoh, *aol, *woh, *wol;
  __nv_bfloat16 *Qbf, *Kbf, *Vhb, *Vlb;
  float *Qb, *Kb, *Vb, *Ab;
  cudaGetSymbolAddress((void**)&hq16, g_hq16);
  cudaGetSymbolAddress((void**)&hk16, g_hk16);
  cudaGetSymbolAddress((void**)&hv16, g_hv16);
  cudaGetSymbolAddress((void**)&wq16, g_wq16);
  cudaGetSymbolAddress((void**)&wk16, g_wk16);
  cudaGetSymbolAddress((void**)&wv16, g_wv16);
  cudaGetSymbolAddress((void**)&aoh, g_ao_h); cudaGetSymbolAddress((void**)&aol, g_ao_l);
  cudaGetSymbolAddress((void**)&woh, g_wo_h); cudaGetSymbolAddress((void**)&wol, g_wo_l);
  cudaGetSymbolAddress((void**)&Qb, g_Q);
  cudaGetSymbolAddress((void**)&Kb, g_K);
  cudaGetSymbolAddress((void**)&Vb, g_V);
  cudaGetSymbolAddress((void**)&Ab, g_A);
  cudaGetSymbolAddress((void**)&Qbf, g_Qbf);
  cudaGetSymbolAddress((void**)&Kbf, g_Kbf);
  cudaGetSymbolAddress((void**)&Vhb, g_Vhb);
  cudaGetSymbolAddress((void**)&Vlb, g_Vlb);

  cudaFuncSetAttribute(gemm_mma_kernel,
                       cudaFuncAttributeMaxDynamicSharedMemorySize, GEMM_SMEM);
  cudaFuncSetAttribute(gemm16_mma_kernel,
                       cudaFuncAttributeMaxDynamicSharedMemorySize, GEMM16_SMEM);
  cudaFuncSetAttribute(flash_mma_kernel,
                       cudaFuncAttributeMaxDynamicSharedMemorySize, FLASH_SMEM);

  // Fused QKV gather + fp16 convert (one pass over hidden)
  gather3_convert_kernel<<<SEQ, 256>>>(hidden, qcol, kcol, vcol,
                                       hq16, hk16, hv16);

  // Weight converts (row-perm folded)
  wconvert16_kernel<<<dim3(4, 4096), 256>>>(Wq, qrow, wq16);
  wconvert16_kernel<<<dim3(4, 1024), 256>>>(Wk, krow, wk16);
  wconvert16_kernel<<<dim3(4, 1024), 256>>>(Wv, vrow, wv16);
  wconvert_kernel<<<dim3(4, 4096), 256>>>(Wo, orow, woh, wol);

  // Q projection (single-pass fp16)
  gemm16_mma_kernel<<<dim3(16, 32, 1), 256, GEMM16_SMEM>>>(
      hq16, wq16, Qb, 4096, hq16, wq16, Qb);
  // K and V projections fused via gridDim.z (single-pass fp16)
  gemm16_mma_kernel<<<dim3(16, 8, 2), 256, GEMM16_SMEM>>>(
      hk16, wk16, Kb, 1024, hv16, wv16, Vb);

  rope_bf16_kernel<<<(SEQ * NH * 64) / 256, 256>>>(Qb, cosp, sinp, Qbf, NH);
  rope_bf16_kernel<<<(SEQ * NKV * 64) / 256, 256>>>(Kb, cosp, sinp, Kbf, NKV);
  vsplit_kernel<<<(SEQ * NKV * HD) / 256, 256>>>(Vb, Vhb, Vlb);

  flash_mma_kernel<<<dim3(SEQ / 64, NH), 128, FLASH_SMEM>>>(Qbf, Kbf, Vhb, Vlb, Ab);

  gather1_convert_kernel<<<SEQ, 256>>>(Ab, ocol, aoh, aol);
  gemm_mma_kernel<<<dim3(16, 32), 256, GEMM_SMEM>>>(
      aoh, aol, woh, wol, (float*)d_out, 4096);
}

// round 11
// speedup vs baseline: 7.9490x; 1.5568x over previous
#include <cuda_runtime.h>
#include <cuda_bf16.h>
#include <cuda_fp16.h>
#include <cstdint>

#define SEQ   2048
#define HDIM  4096
#define NH    32
#define NKV   8
#define HD    128

// ---------------------------------------------------------------------------
// Scratch (__device__ globals; no cudaMalloc allowed)
// ---------------------------------------------------------------------------
__device__ __half g_hq16[SEQ * HDIM], g_hk16[SEQ * HDIM], g_hv16[SEQ * HDIM];
__device__ __half g_wq16[4096 * 4096], g_wk16[1024 * 4096], g_wv16[1024 * 4096];
__device__ __half g_wo16[4096 * 4096];
__device__ __half g_ao16[SEQ * HDIM];
__device__ float g_Q[SEQ * NH * HD];
__device__ float g_K[SEQ * NKV * HD];
__device__ float g_V[SEQ * NKV * HD];
__device__ float g_A[SEQ * NH * HD];
__device__ __half g_Q16[SEQ * NH * HD];
__device__ __half g_K16[SEQ * NKV * HD];
__device__ __half g_V16[SEQ * NKV * HD];

// ---------------------------------------------------------------------------
// PTX helpers (baseline PTX only; works on plain sm_103 target)
// ---------------------------------------------------------------------------
static __device__ __forceinline__ uint32_t smem_u32(const void* p) {
  uint32_t a;
  asm("{ .reg .u64 t; cvta.to.shared.u64 t, %1; cvt.u32.u64 %0, t; }"
      : "=r"(a) : "l"(p));
  return a;
}

#define CP_ASYNC16(dst, src) \
  asm volatile("cp.async.cg.shared.global [%0], [%1], 16;" :: "r"(dst), "l"(src))
#define CP_COMMIT()   asm volatile("cp.async.commit_group;" ::: "memory")
#define CP_WAIT(n)    asm volatile("cp.async.wait_group %0;" :: "n"(n) : "memory")

static __device__ __forceinline__ void ldsm_x4(uint32_t* r, uint32_t addr) {
  asm volatile("ldmatrix.sync.aligned.m8n8.x4.shared.b16 {%0,%1,%2,%3}, [%4];"
               : "=r"(r[0]), "=r"(r[1]), "=r"(r[2]), "=r"(r[3]) : "r"(addr));
}
static __device__ __forceinline__ void ldsm_x4_t(uint32_t* r, uint32_t addr) {
  asm volatile("ldmatrix.sync.aligned.m8n8.x4.trans.shared.b16 {%0,%1,%2,%3}, [%4];"
               : "=r"(r[0]), "=r"(r[1]), "=r"(r[2]), "=r"(r[3]) : "r"(addr));
}

static __device__ __forceinline__ void mma_f16(float* d, const uint32_t* a,
                                               const uint32_t* b) {
  asm volatile(
      "mma.sync.aligned.m16n8k16.row.col.f32.f16.f16.f32 "
      "{%0,%1,%2,%3}, {%4,%5,%6,%7}, {%8,%9}, {%0,%1,%2,%3};"
      : "+f"(d[0]), "+f"(d[1]), "+f"(d[2]), "+f"(d[3])
      : "r"(a[0]), "r"(a[1]), "r"(a[2]), "r"(a[3]), "r"(b[0]), "r"(b[1]));
}

static __device__ __forceinline__ uint32_t pkhf(float a, float b) {
  __half2 t = __floats2half2_rn(a, b);
  return *(uint32_t*)&t;
}

// ---------------------------------------------------------------------------
// Fused 3-way gather + fp16 convert (QKV path): per-row smem staging.
// ---------------------------------------------------------------------------
__global__ void __launch_bounds__(256) gather3_convert_kernel(
    const float* __restrict__ in,
    const int* __restrict__ qi, const int* __restrict__ ki,
    const int* __restrict__ vi,
    __half* __restrict__ q16, __half* __restrict__ k16,
    __half* __restrict__ v16) {
  __shared__ __align__(16) float row[HDIM];
  const int t = blockIdx.x;
  const float* src = in + (size_t)t * HDIM;
#pragma unroll
  for (int i = 0; i < 4; i++) {
    int e = (i * 256 + threadIdx.x) * 4;
    *(float4*)&row[e] = *(const float4*)&src[e];
  }
  __syncthreads();
  const size_t base = (size_t)t * HDIM;
#pragma unroll
  for (int i = 0; i < 16; i++) {
    int c = i * 256 + threadIdx.x;
    q16[base + c] = __float2half_rn(row[qi[c]]);
    k16[base + c] = __float2half_rn(row[ki[c]]);
    v16[base + c] = __float2half_rn(row[vi[c]]);
  }
}

// Single-perm fp16 variant (O path)
__global__ void __launch_bounds__(256) gather1_convert_kernel(
    const float* __restrict__ in, const int* __restrict__ idx,
    __half* __restrict__ o16) {
  __shared__ __align__(16) float row[HDIM];
  const int t = blockIdx.x;
  const float* src = in + (size_t)t * HDIM;
#pragma unroll
  for (int i = 0; i < 4; i++) {
    int e = (i * 256 + threadIdx.x) * 4;
    *(float4*)&row[e] = *(const float4*)&src[e];
  }
  __syncthreads();
  const size_t base = (size_t)t * HDIM;
#pragma unroll
  for (int i = 0; i < 16; i++) {
    int c = i * 256 + threadIdx.x;
    o16[base + c] = __float2half_rn(row[idx[c]]);
  }
}

// ---------------------------------------------------------------------------
// Weight convert fp16 (row-perm folded). grid = (HDIM/1024, nrows)
// ---------------------------------------------------------------------------
__global__ void __launch_bounds__(256) wconvert16_kernel(
    const float* __restrict__ W, const int* __restrict__ ridx,
    __half* __restrict__ o) {
  int j = blockIdx.y;
  int c4 = (blockIdx.x * 256 + threadIdx.x) * 4;
  float4 v = *(const float4*)&W[(size_t)ridx[j] * HDIM + c4];
  uint2 s;
  s.x = pkhf(v.x, v.y); s.y = pkhf(v.z, v.w);
  *(uint2*)&o[(size_t)j * HDIM + c4] = s;
}

// ---------------------------------------------------------------------------
// Single-pass fp16 GEMM: C = A @ B^T, fp32 accum.
// BM=BN=128, BK=32, 8 warps x (32x64). Stage: A(10240B)+B(10240B), x2 buf.
// blockIdx.z selects between two problem sets (K/V fusion).
// ---------------------------------------------------------------------------
#define STAGE16_B 20480
#define GEMM16_SMEM (2 * STAGE16_B)

__global__ void __launch_bounds__(256) gemm16_mma_kernel(
    const __half* A_, const __half* B_, float* C_, int Ntot,
    const __half* A2, const __half* B2, float* C2) {
  const __half* A = A_; const __half* B = B_; float* C = C_;
  if (blockIdx.z == 1) { A = A2; B = B2; C = C2; }

  extern __shared__ __align__(1024) char smem[];
  uint32_t sb = smem_u32(smem);
  const int tid = threadIdx.x, wid = tid >> 5, lane = tid & 31;
  const int row0 = blockIdx.x * 128, col0 = blockIdx.y * 128;

  const __half* ld_src[4];
  uint32_t ld_dst[4];
#pragma unroll
  for (int i = 0; i < 4; i++) {
    int t = i * 256 + tid;
    int mat = t >> 9, r = (t >> 2) & 127, c = t & 3;
    const __half* base = (mat == 0) ? A + (size_t)row0 * 4096
                                    : B + (size_t)col0 * 4096;
    ld_src[i] = base + (size_t)r * 4096 + c * 8;
    ld_dst[i] = (uint32_t)(mat * 10240 + r * 80 + c * 16);
  }

  const int m0 = (wid & 3) * 32, n0 = (wid >> 2) * 64;
  const uint32_t a_lrow = (lane & 7) + ((lane >> 3) & 1) * 8;
  const uint32_t a_lk   = ((lane >> 4) & 1) * 8;
  const uint32_t b_lrow = (lane & 7) + ((lane >> 4) & 1) * 8;
  const uint32_t b_lk   = ((lane >> 3) & 1) * 8;

  float acc[2][8][4];
#pragma unroll
  for (int mt = 0; mt < 2; mt++)
#pragma unroll
    for (int nt = 0; nt < 8; nt++)
#pragma unroll
      for (int j = 0; j < 4; j++) acc[mt][nt][j] = 0.f;

#pragma unroll
  for (int i = 0; i < 4; i++) CP_ASYNC16(sb + ld_dst[i], ld_src[i]);
  CP_COMMIT();

#pragma unroll 1
  for (int kc = 0; kc < 128; kc++) {
    const int p = kc & 1;
    if (kc + 1 < 128) {
      const uint32_t qb = sb + (p ^ 1) * STAGE16_B;
      const int ko = (kc + 1) * 32;
#pragma unroll
      for (int i = 0; i < 4; i++) CP_ASYNC16(qb + ld_dst[i], ld_src[i] + ko);
      CP_COMMIT();
      CP_WAIT(1);
    } else {
      CP_WAIT(0);
    }
    __syncthreads();

    const uint32_t base = sb + p * STAGE16_B;
#pragma unroll
    for (int ks = 0; ks < 32; ks += 16) {
      uint32_t a4[2][4];
#pragma unroll
      for (int mt = 0; mt < 2; mt++)
        ldsm_x4(a4[mt], base + (m0 + mt * 16 + a_lrow) * 80 + (ks + a_lk) * 2);
      uint32_t b4[8][2];
#pragma unroll
      for (int nt2 = 0; nt2 < 4; nt2++) {
        uint32_t t0[4];
        ldsm_x4(t0, base + 10240 + (n0 + nt2 * 16 + b_lrow) * 80 + (ks + b_lk) * 2);
        b4[nt2 * 2][0] = t0[0]; b4[nt2 * 2][1] = t0[1];
        b4[nt2 * 2 + 1][0] = t0[2]; b4[nt2 * 2 + 1][1] = t0[3];
      }
#pragma unroll
      for (int mt = 0; mt < 2; mt++)
#pragma unroll
        for (int nt = 0; nt < 8; nt++)
          mma_f16(acc[mt][nt], a4[mt], b4[nt]);
    }
    __syncthreads();
  }

#pragma unroll
  for (int mt = 0; mt < 2; mt++)
#pragma unroll
    for (int nt = 0; nt < 8; nt++) {
      int m = row0 + m0 + mt * 16 + (lane >> 2);
      int n = col0 + n0 + nt * 8 + (lane & 3) * 2;
      *(float2*)&C[(size_t)m * Ntot + n] =
          make_float2(acc[mt][nt][0], acc[mt][nt][1]);
      *(float2*)&C[(size_t)(m + 8) * Ntot + n] =
          make_float2(acc[mt][nt][2], acc[mt][nt][3]);
    }
}

// ---------------------------------------------------------------------------
// RoPE: fp32 in -> fp16 out
// ---------------------------------------------------------------------------
__global__ void __launch_bounds__(256) rope_f16_kernel(
    const float* __restrict__ x, const float* __restrict__ cs,
    const float* __restrict__ sn, __half* __restrict__ out, int nheads) {
  int idx = blockIdx.x * 256 + threadIdx.x;
  int d = idx & 63;
  int h = (idx >> 6) % nheads;
  int t = idx / (64 * nheads);
  float c1 = cs[t * 128 + d],      s1 = sn[t * 128 + d];
  float c2 = cs[t * 128 + d + 64], s2 = sn[t * 128 + d + 64];
  const float* row = x + (size_t)t * (nheads * 128) + h * 128;
  __half* orow = out + (size_t)t * (nheads * 128) + h * 128;
  float x1 = row[d], x2 = row[d + 64];
  orow[d]      = __float2half_rn(x1 * c1 - x2 * s1);
  orow[d + 64] = __float2half_rn(x2 * c2 + x1 * s2);
}

// V convert: fp32 -> fp16 (vectorized)
__global__ void __launch_bounds__(256) vconvert16_kernel(
    const float* __restrict__ in, __half* __restrict__ o) {
  size_t i4 = ((size_t)blockIdx.x * 256 + threadIdx.x) * 4;
  float4 v = *(const float4*)&in[i4];
  uint2 s;
  s.x = pkhf(v.x, v.y); s.y = pkhf(v.z, v.w);
  *(uint2*)&o[i4] = s;
}

// ---------------------------------------------------------------------------
// Flash attention, all-fp16 mma (QK single-pass, PV single-pass).
// BM=64 q-rows, BN=64 keys, HD=128. 4 warps; warp w owns q-rows [16w,16w+16).
// ---------------------------------------------------------------------------
#define FP 136
#define FLASH_SMEM (3 * 64 * FP * 2)

__global__ void __launch_bounds__(128) flash_mma_kernel(
    const __half* __restrict__ Q16, const __half* __restrict__ K16,
    const __half* __restrict__ V16, float* __restrict__ O) {
  extern __shared__ __align__(1024) char smem[];
  __half* Qs = (__half*)smem;
  __half* Ks = Qs + 64 * FP;
  __half* Vs = Qs + 2 * 64 * FP;

  const int h = blockIdx.y, kvh = h >> 2;
  const int qt = blockIdx.x, qbase = qt * 64;
  const int tid = threadIdx.x, w = tid >> 5, lane = tid & 31;
  const float scale = 0.08838834764831845f;

#pragma unroll
  for (int i = 0; i < 8; i++) {
    int idx = i * 128 + tid;
    int r = idx >> 4, c = idx & 15;
    *(float4*)&Qs[r * FP + c * 8] =
        *(const float4*)&Q16[(size_t)(qbase + r) * (NH * HD) + h * HD + c * 8];
  }
  __syncthreads();

  const uint32_t a_lrow = (lane & 7) + ((lane >> 3) & 1) * 8;
  const uint32_t a_lk   = ((lane >> 4) & 1) * 8;
  const uint32_t b_lrow = (lane & 7) + ((lane >> 4) & 1) * 8;
  const uint32_t b_lk   = ((lane >> 3) & 1) * 8;
  uint32_t qa[8][4];
  {
    uint32_t qsb = smem_u32(Qs);
#pragma unroll
    for (int ks = 0; ks < 8; ks++)
      ldsm_x4(qa[ks], qsb + ((w * 16 + a_lrow) * FP + ks * 16 + a_lk) * 2);
  }

  const int row0 = qbase + w * 16 + (lane >> 2);
  const int row1 = row0 + 8;

  float m_i[2] = {-1e30f, -1e30f}, l_i[2] = {0.f, 0.f};
  float o[16][4];
#pragma unroll
  for (int nt = 0; nt < 16; nt++)
#pragma unroll
    for (int j = 0; j < 4; j++) o[nt][j] = 0.f;

  const uint32_t ksb = smem_u32(Ks), vsb = smem_u32(Vs);

#pragma unroll 1
  for (int kt = 0; kt <= qt; kt++) {
    const int kbase = kt * 64;
    __syncthreads();
#pragma unroll
    for (int i = 0; i < 8; i++) {
      int idx = i * 128 + tid;
      int r = idx >> 4, c = idx & 15;
      size_t g = (size_t)(kbase + r) * (NKV * HD) + kvh * HD + c * 8;
      *(float4*)&Ks[r * FP + c * 8] = *(const float4*)&K16[g];
      *(float4*)&Vs[r * FP + c * 8] = *(const float4*)&V16[g];
    }
    __syncthreads();

    float s[8][4];
#pragma unroll
    for (int nt = 0; nt < 8; nt++)
#pragma unroll
      for (int j = 0; j < 4; j++) s[nt][j] = 0.f;
#pragma unroll
    for (int np = 0; np < 4; np++) {
#pragma unroll
      for (int ks = 0; ks < 8; ks++) {
        uint32_t kb[4];
        ldsm_x4(kb, ksb + ((np * 16 + b_lrow) * FP + ks * 16 + b_lk) * 2);
        mma_f16(s[np * 2],     qa[ks], kb);
        mma_f16(s[np * 2 + 1], qa[ks], kb + 2);
      }
    }

    float rm0 = -1e30f, rm1 = -1e30f;
    const bool diag = (kt == qt);
#pragma unroll
    for (int nt = 0; nt < 8; nt++) {
      int c0 = kbase + nt * 8 + (lane & 3) * 2;
#pragma unroll
      for (int j = 0; j < 4; j++) s[nt][j] *= scale;
      if (diag) {
        if (c0     > row0) s[nt][0] = -1e30f;
        if (c0 + 1 > row0) s[nt][1] = -1e30f;
        if (c0     > row1) s[nt][2] = -1e30f;
        if (c0 + 1 > row1) s[nt][3] = -1e30f;
      }
      rm0 = fmaxf(rm0, fmaxf(s[nt][0], s[nt][1]));
      rm1 = fmaxf(rm1, fmaxf(s[nt][2], s[nt][3]));
    }
#pragma unroll
    for (int off = 1; off <= 2; off <<= 1) {
      rm0 = fmaxf(rm0, __shfl_xor_sync(0xffffffffu, rm0, off));
      rm1 = fmaxf(rm1, __shfl_xor_sync(0xffffffffu, rm1, off));
    }
    float mn0 = fmaxf(m_i[0], rm0), mn1 = fmaxf(m_i[1], rm1);
    float cor0 = __expf(m_i[0] - mn0), cor1 = __expf(m_i[1] - mn1);
    float rs0 = 0.f, rs1 = 0.f;
#pragma unroll
    for (int nt = 0; nt < 8; nt++) {
      s[nt][0] = __expf(s[nt][0] - mn0); rs0 += s[nt][0];
      s[nt][1] = __expf(s[nt][1] - mn0); rs0 += s[nt][1];
      s[nt][2] = __expf(s[nt][2] - mn1); rs1 += s[nt][2];
      s[nt][3] = __expf(s[nt][3] - mn1); rs1 += s[nt][3];
    }
#pragma unroll
    for (int off = 1; off <= 2; off <<= 1) {
      rs0 += __shfl_xor_sync(0xffffffffu, rs0, off);
      rs1 += __shfl_xor_sync(0xffffffffu, rs1, off);
    }
    l_i[0] = l_i[0] * cor0 + rs0; m_i[0] = mn0;
    l_i[1] = l_i[1] * cor1 + rs1; m_i[1] = mn1;
#pragma unroll
    for (int nt = 0; nt < 16; nt++) {
      o[nt][0] *= cor0; o[nt][1] *= cor0;
      o[nt][2] *= cor1; o[nt][3] *= cor1;
    }

    // PV: single-pass fp16
#pragma unroll
    for (int kk = 0; kk < 4; kk++) {
      float* p0 = s[kk * 2];
      float* p1 = s[kk * 2 + 1];
      uint32_t ph[4];
      ph[0] = pkhf(p0[0], p0[1]); ph[1] = pkhf(p0[2], p0[3]);
      ph[2] = pkhf(p1[0], p1[1]); ph[3] = pkhf(p1[2], p1[3]);

      uint32_t vro = ((kk * 16 + (lane & 15)) * FP + ((lane >> 4) << 3)) * 2;
#pragma unroll
      for (int ntp = 0; ntp < 8; ntp++) {
        uint32_t v4[4];
        ldsm_x4_t(v4, vsb + vro + ntp * 32);
        mma_f16(o[ntp * 2],     ph, v4);
        mma_f16(o[ntp * 2 + 1], ph, v4 + 2);
      }
    }
  }

  float rl0 = 1.0f / l_i[0], rl1 = 1.0f / l_i[1];
#pragma unroll
  for (int nt = 0; nt < 16; nt++) {
    int col = h * HD + nt * 8 + (lane & 3) * 2;
    *(float2*)&O[(size_t)row0 * (NH * HD) + col] =
        make_float2(o[nt][0] * rl0, o[nt][1] * rl0);
    *(float2*)&O[(size_t)row1 * (NH * HD) + col] =
        make_float2(o[nt][2] * rl1, o[nt][3] * rl1);
  }
}

// ---------------------------------------------------------------------------
// Host launcher
// ---------------------------------------------------------------------------
extern "C" void kernel_launch(void* const* d_in, const int* in_sizes, int n_in,
                              void* d_out, int out_size) {
  const float* hidden = (const float*)d_in[0];
  const float* Wq = (const float*)d_in[1];
  const float* Wk = (const float*)d_in[2];
  const float* Wv = (const float*)d_in[3];
  const float* Wo = (const float*)d_in[4];
  const float* cosp = (const float*)d_in[5];
  const float* sinp = (const float*)d_in[6];
  const int* qcol = (const int*)d_in[8];
  const int* qrow = (const int*)d_in[9];
  const int* kcol = (const int*)d_in[10];
  const int* krow = (const int*)d_in[11];
  const int* vcol = (const int*)d_in[12];
  const int* vrow = (const int*)d_in[13];
  const int* ocol = (const int*)d_in[14];
  const int* orow = (const int*)d_in[15];

  __half *hq16, *hk16, *hv16, *wq16, *wk16, *wv16, *wo16, *ao16;
  __half *Q16, *K16, *V16;
  float *Qb, *Kb, *Vb, *Ab;
  cudaGetSymbolAddress((void**)&hq16, g_hq16);
  cudaGetSymbolAddress((void**)&hk16, g_hk16);
  cudaGetSymbolAddress((void**)&hv16, g_hv16);
  cudaGetSymbolAddress((void**)&wq16, g_wq16);
  cudaGetSymbolAddress((void**)&wk16, g_wk16);
  cudaGetSymbolAddress((void**)&wv16, g_wv16);
  cudaGetSymbolAddress((void**)&wo16, g_wo16);
  cudaGetSymbolAddress((void**)&ao16, g_ao16);
  cudaGetSymbolAddress((void**)&Qb, g_Q);
  cudaGetSymbolAddress((void**)&Kb, g_K);
  cudaGetSymbolAddress((void**)&Vb, g_V);
  cudaGetSymbolAddress((void**)&Ab, g_A);
  cudaGetSymbolAddress((void**)&Q16, g_Q16);
  cudaGetSymbolAddress((void**)&K16, g_K16);
  cudaGetSymbolAddress((void**)&V16, g_V16);

  cudaFuncSetAttribute(gemm16_mma_kernel,
                       cudaFuncAttributeMaxDynamicSharedMemorySize, GEMM16_SMEM);
  cudaFuncSetAttribute(flash_mma_kernel,
                       cudaFuncAttributeMaxDynamicSharedMemorySize, FLASH_SMEM);

  // Fused QKV gather + fp16 convert (one pass over hidden)
  gather3_convert_kernel<<<SEQ, 256>>>(hidden, qcol, kcol, vcol,
                                       hq16, hk16, hv16);

  // Weight converts (row-perm folded)
  wconvert16_kernel<<<dim3(4, 4096), 256>>>(Wq, qrow, wq16);
  wconvert16_kernel<<<dim3(4, 1024), 256>>>(Wk, krow, wk16);
  wconvert16_kernel<<<dim3(4, 1024), 256>>>(Wv, vrow, wv16);
  wconvert16_kernel<<<dim3(4, 4096), 256>>>(Wo, orow, wo16);

  // Q projection (single-pass fp16)
  gemm16_mma_kernel<<<dim3(16, 32, 1), 256, GEMM16_SMEM>>>(
      hq16, wq16, Qb, 4096, hq16, wq16, Qb);
  // K and V projections fused via gridDim.z (single-pass fp16)
  gemm16_mma_kernel<<<dim3(16, 8, 2), 256, GEMM16_SMEM>>>(
      hk16, wk16, Kb, 1024, hv16, wv16, Vb);

  rope_f16_kernel<<<(SEQ * NH * 64) / 256, 256>>>(Qb, cosp, sinp, Q16, NH);
  rope_f16_kernel<<<(SEQ * NKV * 64) / 256, 256>>>(Kb, cosp, sinp, K16, NKV);
  vconvert16_kernel<<<(SEQ * NKV * HD) / 1024, 256>>>(Vb, V16);

  flash_mma_kernel<<<dim3(SEQ / 64, NH), 128, FLASH_SMEM>>>(Q16, K16, V16, Ab);

  // O path: gather+fp16, single-pass fp16 GEMM
  gather1_convert_kernel<<<SEQ, 256>>>(Ab, ocol, ao16);
  gemm16_mma_kernel<<<dim3(16, 32, 1), 256, GEMM16_SMEM>>>(
      ao16, wo16, (float*)d_out, 4096, ao16, wo16, (float*)d_out);
}